// round 8
// baseline (speedup 1.0000x reference)
#include <cuda_runtime.h>

// ---------------------------------------------------------------------------
// AttentionBlock: out = (X@Wo.T + bo) applied to ctx, + residual; probs output.
// pproc(x,W,b) == x@W.T + b exactly (up to 2 ulps), so plain MHA in fp32.
// B=4, S=2048, H=1024, NH=16, HD=64. No 1/sqrt(d) scaling, no mask.
// Output buffer = [out (B,S,H)] ++ [probs (B,NH,S,S)], both fp32.
// ---------------------------------------------------------------------------

namespace {
constexpr int B_  = 4;
constexpr int S_  = 2048;
constexpr int H_  = 1024;
constexpr int NH_ = 16;
constexpr int HD_ = 64;
constexpr int M_  = B_ * S_;          // 8192 rows
constexpr int BH_ = B_ * NH_;         // 64 (batch*heads)
constexpr long long OUT_ELEMS   = (long long)M_ * H_;          // 8388608
constexpr long long PROBS_ELEMS = (long long)BH_ * S_ * S_;    // 268435456
}

// Scratch (device globals: allocation-free per harness rules)
__device__ float g_q[M_ * H_];          // [BH][S][HD]
__device__ float g_k[M_ * H_];          // [BH][S][HD]
__device__ float g_v[M_ * H_];          // [BH][S][HD]
__device__ float g_ctx[M_ * H_];        // [B,S,H] (heads re-merged)
// Fallback in case the harness output buffer only holds `out` (probs not compared)
__device__ float g_probs_fallback[268435456];

// ---------------- packed f32x2 FMA helpers (FFMA2: 2x fp32 rate) ----------
typedef unsigned long long u64;

__device__ __forceinline__ u64 pk2(float lo, float hi) {
    u64 r;
    asm("mov.b64 %0, {%1, %2};" : "=l"(r) : "f"(lo), "f"(hi));
    return r;
}
__device__ __forceinline__ void fma2(u64& d, u64 a, u64 b) {
    asm("fma.rn.f32x2 %0, %1, %2, %0;" : "+l"(d) : "l"(a), "l"(b));
}
__device__ __forceinline__ float2 up2(u64 v) {
    float2 r;
    asm("mov.b64 {%0, %1}, %2;" : "=f"(r.x), "=f"(r.y) : "l"(v));
    return r;
}

// Bank-permuted smem index for the B operand so that per-kk b64 reads by
// 16 threads (stride-8-float tiles) become 16 contiguous float2s.
// n in [0,128): pos = (p*16 + t)*2 + e  where n = t*8 + 2p + e.
__device__ __forceinline__ int bperm128(int n) {
    return ((((n >> 1) & 3) << 4) + (n >> 3)) * 2 + (n & 1);
}
// Same for 64-wide B tiles (8 threads of 8 floats).
__device__ __forceinline__ int bperm64(int n) {
    return ((((n >> 1) & 3) << 3) + (n >> 3)) * 2 + (n & 1);
}

// ---------------------------------------------------------------------------
// Kernel 1: QKV projection.  out(sel)[b,h,s,d] = sum_k X[m,k] W[n,k] + bias[n]
// X [8192,1024] row-major, W [1024,1024] row-major. 128x128 tile, BK=16,
// 256 threads, 8x8 per thread (f32x2 pairs along n).
// ---------------------------------------------------------------------------
__global__ void __launch_bounds__(256) proj_qkv_kernel(
    const float* __restrict__ X,
    const float* __restrict__ W,
    const float* __restrict__ bias,
    int sel)
{
    float* out = (sel == 0) ? g_q : (sel == 1) ? g_k : g_v;

    __shared__ __align__(16) float As[16 * 128];
    __shared__ __align__(16) float Bs[16 * 128];

    const int tid = threadIdx.x;
    const int n0  = blockIdx.x * 128;
    const int m0  = blockIdx.y * 128;
    const int tx  = tid & 15;
    const int ty  = tid >> 4;

    u64 acc[8][4];
#pragma unroll
    for (int i = 0; i < 8; i++)
#pragma unroll
        for (int p = 0; p < 4; p++) acc[i][p] = 0ULL;

    for (int k0 = 0; k0 < H_; k0 += 16) {
#pragma unroll
        for (int t = 0; t < 2; t++) {
            int idx = tid + t * 256;
            int row = idx >> 2;
            int c4  = (idx & 3) * 4;
            float4 a = *(const float4*)(X + (size_t)(m0 + row) * H_ + k0 + c4);
            As[(c4 + 0) * 128 + row] = a.x;
            As[(c4 + 1) * 128 + row] = a.y;
            As[(c4 + 2) * 128 + row] = a.z;
            As[(c4 + 3) * 128 + row] = a.w;
            float4 w = *(const float4*)(W + (size_t)(n0 + row) * H_ + k0 + c4);
            int bp = bperm128(row);
            Bs[(c4 + 0) * 128 + bp] = w.x;
            Bs[(c4 + 1) * 128 + bp] = w.y;
            Bs[(c4 + 2) * 128 + bp] = w.z;
            Bs[(c4 + 3) * 128 + bp] = w.w;
        }
        __syncthreads();
#pragma unroll
        for (int kk = 0; kk < 16; kk++) {
            float4 a0 = *(const float4*)&As[kk * 128 + ty * 8];
            float4 a1 = *(const float4*)&As[kk * 128 + ty * 8 + 4];
            u64 ad[8];
            ad[0] = pk2(a0.x, a0.x); ad[1] = pk2(a0.y, a0.y);
            ad[2] = pk2(a0.z, a0.z); ad[3] = pk2(a0.w, a0.w);
            ad[4] = pk2(a1.x, a1.x); ad[5] = pk2(a1.y, a1.y);
            ad[6] = pk2(a1.z, a1.z); ad[7] = pk2(a1.w, a1.w);
            u64 b0 = *(const u64*)&Bs[kk * 128 + (0 * 16 + tx) * 2];
            u64 b1 = *(const u64*)&Bs[kk * 128 + (1 * 16 + tx) * 2];
            u64 b2 = *(const u64*)&Bs[kk * 128 + (2 * 16 + tx) * 2];
            u64 b3 = *(const u64*)&Bs[kk * 128 + (3 * 16 + tx) * 2];
#pragma unroll
            for (int i = 0; i < 8; i++) {
                fma2(acc[i][0], ad[i], b0);
                fma2(acc[i][1], ad[i], b1);
                fma2(acc[i][2], ad[i], b2);
                fma2(acc[i][3], ad[i], b3);
            }
        }
        __syncthreads();
    }

#pragma unroll
    for (int i = 0; i < 8; i++) {
        int m = m0 + ty * 8 + i;
        int b = m >> 11;           // / S_
        int s = m & (S_ - 1);
#pragma unroll
        for (int p = 0; p < 4; p++) {
            float2 v = up2(acc[i][p]);
            int n = n0 + tx * 8 + 2 * p;   // even; pair stays within a head
            int h = n >> 6;
            int d = n & 63;
            float2 bb = *(const float2*)(bias + n);
            v.x += bb.x;
            v.y += bb.y;
            *(float2*)(out + ((size_t)((b * NH_ + h) * S_ + s)) * HD_ + d) = v;
        }
    }
}

// ---------------------------------------------------------------------------
// Kernel 2: scores per (b,h): S[i,j] = sum_d Q[i,d] K[j,d]. Raw scores are
// written straight into the probs region (normalized in-place later).
// ---------------------------------------------------------------------------
__global__ void __launch_bounds__(256) scores_kernel(float* __restrict__ probs)
{
    __shared__ __align__(16) float As[16 * 128];
    __shared__ __align__(16) float Bs[16 * 128];

    const int tid = threadIdx.x;
    const int n0  = blockIdx.x * 128;
    const int m0  = blockIdx.y * 128;
    const int bh  = blockIdx.z;
    const float* Q = g_q + (size_t)bh * S_ * HD_;
    const float* K = g_k + (size_t)bh * S_ * HD_;
    float* P = probs + (size_t)bh * S_ * S_;

    const int tx = tid & 15;
    const int ty = tid >> 4;

    u64 acc[8][4];
#pragma unroll
    for (int i = 0; i < 8; i++)
#pragma unroll
        for (int p = 0; p < 4; p++) acc[i][p] = 0ULL;

    for (int k0 = 0; k0 < HD_; k0 += 16) {
#pragma unroll
        for (int t = 0; t < 2; t++) {
            int idx = tid + t * 256;
            int row = idx >> 2;
            int c4  = (idx & 3) * 4;
            float4 a = *(const float4*)(Q + (size_t)(m0 + row) * HD_ + k0 + c4);
            As[(c4 + 0) * 128 + row] = a.x;
            As[(c4 + 1) * 128 + row] = a.y;
            As[(c4 + 2) * 128 + row] = a.z;
            As[(c4 + 3) * 128 + row] = a.w;
            float4 w = *(const float4*)(K + (size_t)(n0 + row) * HD_ + k0 + c4);
            int bp = bperm128(row);
            Bs[(c4 + 0) * 128 + bp] = w.x;
            Bs[(c4 + 1) * 128 + bp] = w.y;
            Bs[(c4 + 2) * 128 + bp] = w.z;
            Bs[(c4 + 3) * 128 + bp] = w.w;
        }
        __syncthreads();
#pragma unroll
        for (int kk = 0; kk < 16; kk++) {
            float4 a0 = *(const float4*)&As[kk * 128 + ty * 8];
            float4 a1 = *(const float4*)&As[kk * 128 + ty * 8 + 4];
            u64 ad[8];
            ad[0] = pk2(a0.x, a0.x); ad[1] = pk2(a0.y, a0.y);
            ad[2] = pk2(a0.z, a0.z); ad[3] = pk2(a0.w, a0.w);
            ad[4] = pk2(a1.x, a1.x); ad[5] = pk2(a1.y, a1.y);
            ad[6] = pk2(a1.z, a1.z); ad[7] = pk2(a1.w, a1.w);
            u64 b0 = *(const u64*)&Bs[kk * 128 + (0 * 16 + tx) * 2];
            u64 b1 = *(const u64*)&Bs[kk * 128 + (1 * 16 + tx) * 2];
            u64 b2 = *(const u64*)&Bs[kk * 128 + (2 * 16 + tx) * 2];
            u64 b3 = *(const u64*)&Bs[kk * 128 + (3 * 16 + tx) * 2];
#pragma unroll
            for (int i = 0; i < 8; i++) {
                fma2(acc[i][0], ad[i], b0);
                fma2(acc[i][1], ad[i], b1);
                fma2(acc[i][2], ad[i], b2);
                fma2(acc[i][3], ad[i], b3);
            }
        }
        __syncthreads();
    }

#pragma unroll
    for (int i = 0; i < 8; i++) {
        int m = m0 + ty * 8 + i;
#pragma unroll
        for (int p = 0; p < 4; p++) {
            float2 v = up2(acc[i][p]);
            int n = n0 + tx * 8 + 2 * p;
            *(float2*)(P + (size_t)m * S_ + n) = v;
        }
    }
}

// ---------------------------------------------------------------------------
// Kernel 3: in-place row softmax on probs. One block per row; the 2048-float
// row lives in registers (8/thread).
// ---------------------------------------------------------------------------
__global__ void __launch_bounds__(256) softmax_kernel(float* __restrict__ probs)
{
    __shared__ float redmax[8];
    __shared__ float redsum[8];

    float* p = probs + ((size_t)blockIdx.y * S_ + blockIdx.x) * S_;
    const int tid = threadIdx.x;

    float4 x0 = *(const float4*)(p + tid * 8);
    float4 x1 = *(const float4*)(p + tid * 8 + 4);
    float v[8] = {x0.x, x0.y, x0.z, x0.w, x1.x, x1.y, x1.z, x1.w};

    float mx = v[0];
#pragma unroll
    for (int i = 1; i < 8; i++) mx = fmaxf(mx, v[i]);
#pragma unroll
    for (int o = 16; o; o >>= 1) mx = fmaxf(mx, __shfl_xor_sync(0xffffffffu, mx, o));
    if ((tid & 31) == 0) redmax[tid >> 5] = mx;
    __syncthreads();
    mx = redmax[0];
#pragma unroll
    for (int i = 1; i < 8; i++) mx = fmaxf(mx, redmax[i]);

    float s = 0.f;
#pragma unroll
    for (int i = 0; i < 8; i++) {
        v[i] = __expf(v[i] - mx);
        s += v[i];
    }
#pragma unroll
    for (int o = 16; o; o >>= 1) s += __shfl_xor_sync(0xffffffffu, s, o);
    if ((tid & 31) == 0) redsum[tid >> 5] = s;
    __syncthreads();
    s = 0.f;
#pragma unroll
    for (int i = 0; i < 8; i++) s += redsum[i];

    float inv = 1.0f / s;
#pragma unroll
    for (int i = 0; i < 8; i++) v[i] *= inv;
    *(float4*)(p + tid * 8)     = make_float4(v[0], v[1], v[2], v[3]);
    *(float4*)(p + tid * 8 + 4) = make_float4(v[4], v[5], v[6], v[7]);
}

// ---------------------------------------------------------------------------
// Kernel 4: ctx = probs @ V per (b,h). M=2048, N=64, K=2048. 128 threads,
// 128x64 tile, 8x8 per thread. Writes ctx merged as [B,S,H].
// ---------------------------------------------------------------------------
__global__ void __launch_bounds__(128) ctx_kernel(const float* __restrict__ probs)
{
    __shared__ __align__(16) float As[16 * 128];
    __shared__ __align__(16) float Bs[16 * 64];

    const int tid = threadIdx.x;
    const int m0  = blockIdx.x * 128;
    const int bh  = blockIdx.y;
    const float* P = probs + (size_t)bh * S_ * S_;
    const float* V = g_v + (size_t)bh * S_ * HD_;

    const int tx = tid & 7;
    const int ty = tid >> 3;

    u64 acc[8][4];
#pragma unroll
    for (int i = 0; i < 8; i++)
#pragma unroll
        for (int p = 0; p < 4; p++) acc[i][p] = 0ULL;

    for (int k0 = 0; k0 < S_; k0 += 16) {
#pragma unroll
        for (int t = 0; t < 4; t++) {
            int idx = tid + t * 128;
            int row = idx >> 2;
            int c4  = (idx & 3) * 4;
            float4 a = *(const float4*)(P + (size_t)(m0 + row) * S_ + k0 + c4);
            As[(c4 + 0) * 128 + row] = a.x;
            As[(c4 + 1) * 128 + row] = a.y;
            As[(c4 + 2) * 128 + row] = a.z;
            As[(c4 + 3) * 128 + row] = a.w;
        }
#pragma unroll
        for (int t = 0; t < 2; t++) {
            int idx = tid + t * 128;
            int jr  = idx >> 4;                 // 0..15 (k within tile)
            int dc  = (idx & 15) * 4;           // 0..60
            float4 b = *(const float4*)(V + (size_t)(k0 + jr) * HD_ + dc);
            Bs[jr * 64 + bperm64(dc + 0)] = b.x;
            Bs[jr * 64 + bperm64(dc + 1)] = b.y;
            Bs[jr * 64 + bperm64(dc + 2)] = b.z;
            Bs[jr * 64 + bperm64(dc + 3)] = b.w;
        }
        __syncthreads();
#pragma unroll
        for (int kk = 0; kk < 16; kk++) {
            float4 a0 = *(const float4*)&As[kk * 128 + ty * 8];
            float4 a1 = *(const float4*)&As[kk * 128 + ty * 8 + 4];
            u64 ad[8];
            ad[0] = pk2(a0.x, a0.x); ad[1] = pk2(a0.y, a0.y);
            ad[2] = pk2(a0.z, a0.z); ad[3] = pk2(a0.w, a0.w);
            ad[4] = pk2(a1.x, a1.x); ad[5] = pk2(a1.y, a1.y);
            ad[6] = pk2(a1.z, a1.z); ad[7] = pk2(a1.w, a1.w);
            u64 b0 = *(const u64*)&Bs[kk * 64 + (0 * 8 + tx) * 2];
            u64 b1 = *(const u64*)&Bs[kk * 64 + (1 * 8 + tx) * 2];
            u64 b2 = *(const u64*)&Bs[kk * 64 + (2 * 8 + tx) * 2];
            u64 b3 = *(const u64*)&Bs[kk * 64 + (3 * 8 + tx) * 2];
#pragma unroll
            for (int i = 0; i < 8; i++) {
                fma2(acc[i][0], ad[i], b0);
                fma2(acc[i][1], ad[i], b1);
                fma2(acc[i][2], ad[i], b2);
                fma2(acc[i][3], ad[i], b3);
            }
        }
        __syncthreads();
    }

    const int b = bh >> 4;
    const int h = bh & 15;
#pragma unroll
    for (int i = 0; i < 8; i++) {
        int s = m0 + ty * 8 + i;
#pragma unroll
        for (int p = 0; p < 4; p++) {
            float2 v = up2(acc[i][p]);
            int d = tx * 8 + 2 * p;
            *(float2*)(g_ctx + ((size_t)(b * S_ + s)) * H_ + h * HD_ + d) = v;
        }
    }
}

// ---------------------------------------------------------------------------
// Kernel 5: out[m,n] = sum_k ctx[m,k] Wo[n,k] + bo[n] + hidden[m,n]
// ---------------------------------------------------------------------------
__global__ void __launch_bounds__(256) outproj_kernel(
    const float* __restrict__ W,
    const float* __restrict__ bias,
    const float* __restrict__ hid,
    float* __restrict__ out)
{
    __shared__ __align__(16) float As[16 * 128];
    __shared__ __align__(16) float Bs[16 * 128];

    const int tid = threadIdx.x;
    const int n0  = blockIdx.x * 128;
    const int m0  = blockIdx.y * 128;
    const int tx  = tid & 15;
    const int ty  = tid >> 4;

    u64 acc[8][4];
#pragma unroll
    for (int i = 0; i < 8; i++)
#pragma unroll
        for (int p = 0; p < 4; p++) acc[i][p] = 0ULL;

    for (int k0 = 0; k0 < H_; k0 += 16) {
#pragma unroll
        for (int t = 0; t < 2; t++) {
            int idx = tid + t * 256;
            int row = idx >> 2;
            int c4  = (idx & 3) * 4;
            float4 a = *(const float4*)(g_ctx + (size_t)(m0 + row) * H_ + k0 + c4);
            As[(c4 + 0) * 128 + row] = a.x;
            As[(c4 + 1) * 128 + row] = a.y;
            As[(c4 + 2) * 128 + row] = a.z;
            As[(c4 + 3) * 128 + row] = a.w;
            float4 w = *(const float4*)(W + (size_t)(n0 + row) * H_ + k0 + c4);
            int bp = bperm128(row);
            Bs[(c4 + 0) * 128 + bp] = w.x;
            Bs[(c4 + 1) * 128 + bp] = w.y;
            Bs[(c4 + 2) * 128 + bp] = w.z;
            Bs[(c4 + 3) * 128 + bp] = w.w;
        }
        __syncthreads();
#pragma unroll
        for (int kk = 0; kk < 16; kk++) {
            float4 a0 = *(const float4*)&As[kk * 128 + ty * 8];
            float4 a1 = *(const float4*)&As[kk * 128 + ty * 8 + 4];
            u64 ad[8];
            ad[0] = pk2(a0.x, a0.x); ad[1] = pk2(a0.y, a0.y);
            ad[2] = pk2(a0.z, a0.z); ad[3] = pk2(a0.w, a0.w);
            ad[4] = pk2(a1.x, a1.x); ad[5] = pk2(a1.y, a1.y);
            ad[6] = pk2(a1.z, a1.z); ad[7] = pk2(a1.w, a1.w);
            u64 b0 = *(const u64*)&Bs[kk * 128 + (0 * 16 + tx) * 2];
            u64 b1 = *(const u64*)&Bs[kk * 128 + (1 * 16 + tx) * 2];
            u64 b2 = *(const u64*)&Bs[kk * 128 + (2 * 16 + tx) * 2];
            u64 b3 = *(const u64*)&Bs[kk * 128 + (3 * 16 + tx) * 2];
#pragma unroll
            for (int i = 0; i < 8; i++) {
                fma2(acc[i][0], ad[i], b0);
                fma2(acc[i][1], ad[i], b1);
                fma2(acc[i][2], ad[i], b2);
                fma2(acc[i][3], ad[i], b3);
            }
        }
        __syncthreads();
    }

#pragma unroll
    for (int i = 0; i < 8; i++) {
        int m = m0 + ty * 8 + i;
#pragma unroll
        for (int p = 0; p < 4; p++) {
            float2 v = up2(acc[i][p]);
            int n = n0 + tx * 8 + 2 * p;
            float2 bb = *(const float2*)(bias + n);
            float2 hh = *(const float2*)(hid + (size_t)m * H_ + n);
            v.x += bb.x + hh.x;
            v.y += bb.y + hh.y;
            *(float2*)(out + (size_t)m * H_ + n) = v;
        }
    }
}

// ---------------------------------------------------------------------------
extern "C" void kernel_launch(void* const* d_in, const int* in_sizes, int n_in,
                              void* d_out, int out_size)
{
    (void)in_sizes; (void)n_in;

    const float* hs = (const float*)d_in[0];
    const float* Wq = (const float*)d_in[1];
    const float* bq = (const float*)d_in[2];
    const float* Wk = (const float*)d_in[3];
    const float* bk = (const float*)d_in[4];
    const float* Wv = (const float*)d_in[5];
    const float* bv = (const float*)d_in[6];
    const float* Wo = (const float*)d_in[7];
    const float* bo = (const float*)d_in[8];
    float* out = (float*)d_out;

    // probs live in the output buffer (flattened tuple: out then probs);
    // fall back to device scratch if the harness buffer only holds `out`.
    float* probs;
    if ((long long)out_size >= OUT_ELEMS + PROBS_ELEMS) {
        probs = out + OUT_ELEMS;
    } else {
        void* p = nullptr;
        cudaGetSymbolAddress(&p, g_probs_fallback);
        probs = (float*)p;
    }

    const dim3 gProj(H_ / 128, M_ / 128);           // (8, 64)
    proj_qkv_kernel<<<gProj, 256>>>(hs, Wq, bq, 0);
    proj_qkv_kernel<<<gProj, 256>>>(hs, Wk, bk, 1);
    proj_qkv_kernel<<<gProj, 256>>>(hs, Wv, bv, 2);

    scores_kernel<<<dim3(S_ / 128, S_ / 128, BH_), 256>>>(probs);   // (16,16,64)
    softmax_kernel<<<dim3(S_, BH_), 256>>>(probs);                  // (2048,64)
    ctx_kernel<<<dim3(S_ / 128, BH_), 128>>>(probs);                // (16,64)
    outproj_kernel<<<gProj, 256>>>(Wo, bo, hs, out);
}

// round 9
// speedup vs baseline: 1.0004x; 1.0004x over previous
#include <cuda_runtime.h>

// ---------------------------------------------------------------------------
// AttentionBlock: out = (X@Wo.T + bo) applied to ctx, + residual; probs output.
// pproc(x,W,b) == x@W.T + b exactly (up to 2 ulps), so plain MHA in fp32.
// B=4, S=2048, H=1024, NH=16, HD=64. No 1/sqrt(d) scaling, no mask.
// Output buffer = [out (B,S,H)] ++ [probs (B,NH,S,S)], both fp32.
// ---------------------------------------------------------------------------

namespace {
constexpr int B_  = 4;
constexpr int S_  = 2048;
constexpr int H_  = 1024;
constexpr int NH_ = 16;
constexpr int HD_ = 64;
constexpr int M_  = B_ * S_;          // 8192 rows
constexpr int BH_ = B_ * NH_;         // 64 (batch*heads)
constexpr long long OUT_ELEMS   = (long long)M_ * H_;          // 8388608
constexpr long long PROBS_ELEMS = (long long)BH_ * S_ * S_;    // 268435456
}

// Scratch (device globals: allocation-free per harness rules)
__device__ float g_q[M_ * H_];          // [BH][S][HD]
__device__ float g_k[M_ * H_];          // [BH][S][HD]
__device__ float g_v[M_ * H_];          // [BH][S][HD]
__device__ float g_ctx[M_ * H_];        // [B,S,H] (heads re-merged)
// Fallback in case the harness output buffer only holds `out` (probs not compared)
__device__ float g_probs_fallback[268435456];

// ---------------- packed f32x2 FMA helpers (FFMA2: 2x fp32 rate) ----------
typedef unsigned long long u64;

__device__ __forceinline__ u64 pk2(float lo, float hi) {
    u64 r;
    asm("mov.b64 %0, {%1, %2};" : "=l"(r) : "f"(lo), "f"(hi));
    return r;
}
__device__ __forceinline__ void fma2(u64& d, u64 a, u64 b) {
    asm("fma.rn.f32x2 %0, %1, %2, %0;" : "+l"(d) : "l"(a), "l"(b));
}
__device__ __forceinline__ float2 up2(u64 v) {
    float2 r;
    asm("mov.b64 {%0, %1}, %2;" : "=f"(r.x), "=f"(r.y) : "l"(v));
    return r;
}

// Bank-permuted smem index for the B operand so that per-kk b64 reads by
// 16 threads (stride-8-float tiles) become 16 contiguous float2s.
// n in [0,128): pos = (p*16 + t)*2 + e  where n = t*8 + 2p + e.
__device__ __forceinline__ int bperm128(int n) {
    return ((((n >> 1) & 3) << 4) + (n >> 3)) * 2 + (n & 1);
}
// Same for 64-wide B tiles (8 threads of 8 floats).
__device__ __forceinline__ int bperm64(int n) {
    return ((((n >> 1) & 3) << 3) + (n >> 3)) * 2 + (n & 1);
}

// ---------------------------------------------------------------------------
// Kernel 1: QKV projection.  out(sel)[b,h,s,d] = sum_k X[m,k] W[n,k] + bias[n]
// X [8192,1024] row-major, W [1024,1024] row-major. 128x128 tile, BK=16,
// 256 threads, 8x8 per thread (f32x2 pairs along n).
// ---------------------------------------------------------------------------
__global__ void __launch_bounds__(256) proj_qkv_kernel(
    const float* __restrict__ X,
    const float* __restrict__ W,
    const float* __restrict__ bias,
    int sel)
{
    float* out = (sel == 0) ? g_q : (sel == 1) ? g_k : g_v;

    __shared__ __align__(16) float As[16 * 128];
    __shared__ __align__(16) float Bs[16 * 128];

    const int tid = threadIdx.x;
    const int n0  = blockIdx.x * 128;
    const int m0  = blockIdx.y * 128;
    const int tx  = tid & 15;
    const int ty  = tid >> 4;

    u64 acc[8][4];
#pragma unroll
    for (int i = 0; i < 8; i++)
#pragma unroll
        for (int p = 0; p < 4; p++) acc[i][p] = 0ULL;

    for (int k0 = 0; k0 < H_; k0 += 16) {
#pragma unroll
        for (int t = 0; t < 2; t++) {
            int idx = tid + t * 256;
            int row = idx >> 2;
            int c4  = (idx & 3) * 4;
            float4 a = *(const float4*)(X + (size_t)(m0 + row) * H_ + k0 + c4);
            As[(c4 + 0) * 128 + row] = a.x;
            As[(c4 + 1) * 128 + row] = a.y;
            As[(c4 + 2) * 128 + row] = a.z;
            As[(c4 + 3) * 128 + row] = a.w;
            float4 w = *(const float4*)(W + (size_t)(n0 + row) * H_ + k0 + c4);
            int bp = bperm128(row);
            Bs[(c4 + 0) * 128 + bp] = w.x;
            Bs[(c4 + 1) * 128 + bp] = w.y;
            Bs[(c4 + 2) * 128 + bp] = w.z;
            Bs[(c4 + 3) * 128 + bp] = w.w;
        }
        __syncthreads();
#pragma unroll
        for (int kk = 0; kk < 16; kk++) {
            float4 a0 = *(const float4*)&As[kk * 128 + ty * 8];
            float4 a1 = *(const float4*)&As[kk * 128 + ty * 8 + 4];
            u64 ad[8];
            ad[0] = pk2(a0.x, a0.x); ad[1] = pk2(a0.y, a0.y);
            ad[2] = pk2(a0.z, a0.z); ad[3] = pk2(a0.w, a0.w);
            ad[4] = pk2(a1.x, a1.x); ad[5] = pk2(a1.y, a1.y);
            ad[6] = pk2(a1.z, a1.z); ad[7] = pk2(a1.w, a1.w);
            u64 b0 = *(const u64*)&Bs[kk * 128 + (0 * 16 + tx) * 2];
            u64 b1 = *(const u64*)&Bs[kk * 128 + (1 * 16 + tx) * 2];
            u64 b2 = *(const u64*)&Bs[kk * 128 + (2 * 16 + tx) * 2];
            u64 b3 = *(const u64*)&Bs[kk * 128 + (3 * 16 + tx) * 2];
#pragma unroll
            for (int i = 0; i < 8; i++) {
                fma2(acc[i][0], ad[i], b0);
                fma2(acc[i][1], ad[i], b1);
                fma2(acc[i][2], ad[i], b2);
                fma2(acc[i][3], ad[i], b3);
            }
        }
        __syncthreads();
    }

#pragma unroll
    for (int i = 0; i < 8; i++) {
        int m = m0 + ty * 8 + i;
        int b = m >> 11;           // / S_
        int s = m & (S_ - 1);
#pragma unroll
        for (int p = 0; p < 4; p++) {
            float2 v = up2(acc[i][p]);
            int n = n0 + tx * 8 + 2 * p;   // even; pair stays within a head
            int h = n >> 6;
            int d = n & 63;
            float2 bb = *(const float2*)(bias + n);
            v.x += bb.x;
            v.y += bb.y;
            *(float2*)(out + ((size_t)((b * NH_ + h) * S_ + s)) * HD_ + d) = v;
        }
    }
}

// ---------------------------------------------------------------------------
// Kernel 2: scores per (b,h): S[i,j] = sum_d Q[i,d] K[j,d]. Raw scores are
// written straight into the probs region (normalized in-place later).
// ---------------------------------------------------------------------------
__global__ void __launch_bounds__(256) scores_kernel(float* __restrict__ probs)
{
    __shared__ __align__(16) float As[16 * 128];
    __shared__ __align__(16) float Bs[16 * 128];

    const int tid = threadIdx.x;
    const int n0  = blockIdx.x * 128;
    const int m0  = blockIdx.y * 128;
    const int bh  = blockIdx.z;
    const float* Q = g_q + (size_t)bh * S_ * HD_;
    const float* K = g_k + (size_t)bh * S_ * HD_;
    float* P = probs + (size_t)bh * S_ * S_;

    const int tx = tid & 15;
    const int ty = tid >> 4;

    u64 acc[8][4];
#pragma unroll
    for (int i = 0; i < 8; i++)
#pragma unroll
        for (int p = 0; p < 4; p++) acc[i][p] = 0ULL;

    for (int k0 = 0; k0 < HD_; k0 += 16) {
#pragma unroll
        for (int t = 0; t < 2; t++) {
            int idx = tid + t * 256;
            int row = idx >> 2;
            int c4  = (idx & 3) * 4;
            float4 a = *(const float4*)(Q + (size_t)(m0 + row) * HD_ + k0 + c4);
            As[(c4 + 0) * 128 + row] = a.x;
            As[(c4 + 1) * 128 + row] = a.y;
            As[(c4 + 2) * 128 + row] = a.z;
            As[(c4 + 3) * 128 + row] = a.w;
            float4 w = *(const float4*)(K + (size_t)(n0 + row) * HD_ + k0 + c4);
            int bp = bperm128(row);
            Bs[(c4 + 0) * 128 + bp] = w.x;
            Bs[(c4 + 1) * 128 + bp] = w.y;
            Bs[(c4 + 2) * 128 + bp] = w.z;
            Bs[(c4 + 3) * 128 + bp] = w.w;
        }
        __syncthreads();
#pragma unroll
        for (int kk = 0; kk < 16; kk++) {
            float4 a0 = *(const float4*)&As[kk * 128 + ty * 8];
            float4 a1 = *(const float4*)&As[kk * 128 + ty * 8 + 4];
            u64 ad[8];
            ad[0] = pk2(a0.x, a0.x); ad[1] = pk2(a0.y, a0.y);
            ad[2] = pk2(a0.z, a0.z); ad[3] = pk2(a0.w, a0.w);
            ad[4] = pk2(a1.x, a1.x); ad[5] = pk2(a1.y, a1.y);
            ad[6] = pk2(a1.z, a1.z); ad[7] = pk2(a1.w, a1.w);
            u64 b0 = *(const u64*)&Bs[kk * 128 + (0 * 16 + tx) * 2];
            u64 b1 = *(const u64*)&Bs[kk * 128 + (1 * 16 + tx) * 2];
            u64 b2 = *(const u64*)&Bs[kk * 128 + (2 * 16 + tx) * 2];
            u64 b3 = *(const u64*)&Bs[kk * 128 + (3 * 16 + tx) * 2];
#pragma unroll
            for (int i = 0; i < 8; i++) {
                fma2(acc[i][0], ad[i], b0);
                fma2(acc[i][1], ad[i], b1);
                fma2(acc[i][2], ad[i], b2);
                fma2(acc[i][3], ad[i], b3);
            }
        }
        __syncthreads();
    }

#pragma unroll
    for (int i = 0; i < 8; i++) {
        int m = m0 + ty * 8 + i;
#pragma unroll
        for (int p = 0; p < 4; p++) {
            float2 v = up2(acc[i][p]);
            int n = n0 + tx * 8 + 2 * p;
            *(float2*)(P + (size_t)m * S_ + n) = v;
        }
    }
}

// ---------------------------------------------------------------------------
// Kernel 3: in-place row softmax on probs. One block per row; the 2048-float
// row lives in registers (8/thread).
// ---------------------------------------------------------------------------
__global__ void __launch_bounds__(256) softmax_kernel(float* __restrict__ probs)
{
    __shared__ float redmax[8];
    __shared__ float redsum[8];

    float* p = probs + ((size_t)blockIdx.y * S_ + blockIdx.x) * S_;
    const int tid = threadIdx.x;

    float4 x0 = *(const float4*)(p + tid * 8);
    float4 x1 = *(const float4*)(p + tid * 8 + 4);
    float v[8] = {x0.x, x0.y, x0.z, x0.w, x1.x, x1.y, x1.z, x1.w};

    float mx = v[0];
#pragma unroll
    for (int i = 1; i < 8; i++) mx = fmaxf(mx, v[i]);
#pragma unroll
    for (int o = 16; o; o >>= 1) mx = fmaxf(mx, __shfl_xor_sync(0xffffffffu, mx, o));
    if ((tid & 31) == 0) redmax[tid >> 5] = mx;
    __syncthreads();
    mx = redmax[0];
#pragma unroll
    for (int i = 1; i < 8; i++) mx = fmaxf(mx, redmax[i]);

    float s = 0.f;
#pragma unroll
    for (int i = 0; i < 8; i++) {
        v[i] = __expf(v[i] - mx);
        s += v[i];
    }
#pragma unroll
    for (int o = 16; o; o >>= 1) s += __shfl_xor_sync(0xffffffffu, s, o);
    if ((tid & 31) == 0) redsum[tid >> 5] = s;
    __syncthreads();
    s = 0.f;
#pragma unroll
    for (int i = 0; i < 8; i++) s += redsum[i];

    float inv = 1.0f / s;
#pragma unroll
    for (int i = 0; i < 8; i++) v[i] *= inv;
    *(float4*)(p + tid * 8)     = make_float4(v[0], v[1], v[2], v[3]);
    *(float4*)(p + tid * 8 + 4) = make_float4(v[4], v[5], v[6], v[7]);
}

// ---------------------------------------------------------------------------
// Kernel 4: ctx = probs @ V per (b,h). M=2048, N=64, K=2048. 128 threads,
// 128x64 tile, 8x8 per thread. Writes ctx merged as [B,S,H].
// ---------------------------------------------------------------------------
__global__ void __launch_bounds__(128) ctx_kernel(const float* __restrict__ probs)
{
    __shared__ __align__(16) float As[16 * 128];
    __shared__ __align__(16) float Bs[16 * 64];

    const int tid = threadIdx.x;
    const int m0  = blockIdx.x * 128;
    const int bh  = blockIdx.y;
    const float* P = probs + (size_t)bh * S_ * S_;
    const float* V = g_v + (size_t)bh * S_ * HD_;

    const int tx = tid & 7;
    const int ty = tid >> 3;

    u64 acc[8][4];
#pragma unroll
    for (int i = 0; i < 8; i++)
#pragma unroll
        for (int p = 0; p < 4; p++) acc[i][p] = 0ULL;

    for (int k0 = 0; k0 < S_; k0 += 16) {
#pragma unroll
        for (int t = 0; t < 4; t++) {
            int idx = tid + t * 128;
            int row = idx >> 2;
            int c4  = (idx & 3) * 4;
            float4 a = *(const float4*)(P + (size_t)(m0 + row) * S_ + k0 + c4);
            As[(c4 + 0) * 128 + row] = a.x;
            As[(c4 + 1) * 128 + row] = a.y;
            As[(c4 + 2) * 128 + row] = a.z;
            As[(c4 + 3) * 128 + row] = a.w;
        }
#pragma unroll
        for (int t = 0; t < 2; t++) {
            int idx = tid + t * 128;
            int jr  = idx >> 4;                 // 0..15 (k within tile)
            int dc  = (idx & 15) * 4;           // 0..60
            float4 b = *(const float4*)(V + (size_t)(k0 + jr) * HD_ + dc);
            Bs[jr * 64 + bperm64(dc + 0)] = b.x;
            Bs[jr * 64 + bperm64(dc + 1)] = b.y;
            Bs[jr * 64 + bperm64(dc + 2)] = b.z;
            Bs[jr * 64 + bperm64(dc + 3)] = b.w;
        }
        __syncthreads();
#pragma unroll
        for (int kk = 0; kk < 16; kk++) {
            float4 a0 = *(const float4*)&As[kk * 128 + ty * 8];
            float4 a1 = *(const float4*)&As[kk * 128 + ty * 8 + 4];
            u64 ad[8];
            ad[0] = pk2(a0.x, a0.x); ad[1] = pk2(a0.y, a0.y);
            ad[2] = pk2(a0.z, a0.z); ad[3] = pk2(a0.w, a0.w);
            ad[4] = pk2(a1.x, a1.x); ad[5] = pk2(a1.y, a1.y);
            ad[6] = pk2(a1.z, a1.z); ad[7] = pk2(a1.w, a1.w);
            u64 b0 = *(const u64*)&Bs[kk * 64 + (0 * 8 + tx) * 2];
            u64 b1 = *(const u64*)&Bs[kk * 64 + (1 * 8 + tx) * 2];
            u64 b2 = *(const u64*)&Bs[kk * 64 + (2 * 8 + tx) * 2];
            u64 b3 = *(const u64*)&Bs[kk * 64 + (3 * 8 + tx) * 2];
#pragma unroll
            for (int i = 0; i < 8; i++) {
                fma2(acc[i][0], ad[i], b0);
                fma2(acc[i][1], ad[i], b1);
                fma2(acc[i][2], ad[i], b2);
                fma2(acc[i][3], ad[i], b3);
            }
        }
        __syncthreads();
    }

    const int b = bh >> 4;
    const int h = bh & 15;
#pragma unroll
    for (int i = 0; i < 8; i++) {
        int s = m0 + ty * 8 + i;
#pragma unroll
        for (int p = 0; p < 4; p++) {
            float2 v = up2(acc[i][p]);
            int d = tx * 8 + 2 * p;
            *(float2*)(g_ctx + ((size_t)(b * S_ + s)) * H_ + h * HD_ + d) = v;
        }
    }
}

// ---------------------------------------------------------------------------
// Kernel 5: out[m,n] = sum_k ctx[m,k] Wo[n,k] + bo[n] + hidden[m,n]
// ---------------------------------------------------------------------------
__global__ void __launch_bounds__(256) outproj_kernel(
    const float* __restrict__ W,
    const float* __restrict__ bias,
    const float* __restrict__ hid,
    float* __restrict__ out)
{
    __shared__ __align__(16) float As[16 * 128];
    __shared__ __align__(16) float Bs[16 * 128];

    const int tid = threadIdx.x;
    const int n0  = blockIdx.x * 128;
    const int m0  = blockIdx.y * 128;
    const int tx  = tid & 15;
    const int ty  = tid >> 4;

    u64 acc[8][4];
#pragma unroll
    for (int i = 0; i < 8; i++)
#pragma unroll
        for (int p = 0; p < 4; p++) acc[i][p] = 0ULL;

    for (int k0 = 0; k0 < H_; k0 += 16) {
#pragma unroll
        for (int t = 0; t < 2; t++) {
            int idx = tid + t * 256;
            int row = idx >> 2;
            int c4  = (idx & 3) * 4;
            float4 a = *(const float4*)(g_ctx + (size_t)(m0 + row) * H_ + k0 + c4);
            As[(c4 + 0) * 128 + row] = a.x;
            As[(c4 + 1) * 128 + row] = a.y;
            As[(c4 + 2) * 128 + row] = a.z;
            As[(c4 + 3) * 128 + row] = a.w;
            float4 w = *(const float4*)(W + (size_t)(n0 + row) * H_ + k0 + c4);
            int bp = bperm128(row);
            Bs[(c4 + 0) * 128 + bp] = w.x;
            Bs[(c4 + 1) * 128 + bp] = w.y;
            Bs[(c4 + 2) * 128 + bp] = w.z;
            Bs[(c4 + 3) * 128 + bp] = w.w;
        }
        __syncthreads();
#pragma unroll
        for (int kk = 0; kk < 16; kk++) {
            float4 a0 = *(const float4*)&As[kk * 128 + ty * 8];
            float4 a1 = *(const float4*)&As[kk * 128 + ty * 8 + 4];
            u64 ad[8];
            ad[0] = pk2(a0.x, a0.x); ad[1] = pk2(a0.y, a0.y);
            ad[2] = pk2(a0.z, a0.z); ad[3] = pk2(a0.w, a0.w);
            ad[4] = pk2(a1.x, a1.x); ad[5] = pk2(a1.y, a1.y);
            ad[6] = pk2(a1.z, a1.z); ad[7] = pk2(a1.w, a1.w);
            u64 b0 = *(const u64*)&Bs[kk * 128 + (0 * 16 + tx) * 2];
            u64 b1 = *(const u64*)&Bs[kk * 128 + (1 * 16 + tx) * 2];
            u64 b2 = *(const u64*)&Bs[kk * 128 + (2 * 16 + tx) * 2];
            u64 b3 = *(const u64*)&Bs[kk * 128 + (3 * 16 + tx) * 2];
#pragma unroll
            for (int i = 0; i < 8; i++) {
                fma2(acc[i][0], ad[i], b0);
                fma2(acc[i][1], ad[i], b1);
                fma2(acc[i][2], ad[i], b2);
                fma2(acc[i][3], ad[i], b3);
            }
        }
        __syncthreads();
    }

#pragma unroll
    for (int i = 0; i < 8; i++) {
        int m = m0 + ty * 8 + i;
#pragma unroll
        for (int p = 0; p < 4; p++) {
            float2 v = up2(acc[i][p]);
            int n = n0 + tx * 8 + 2 * p;
            float2 bb = *(const float2*)(bias + n);
            float2 hh = *(const float2*)(hid + (size_t)m * H_ + n);
            v.x += bb.x + hh.x;
            v.y += bb.y + hh.y;
            *(float2*)(out + (size_t)m * H_ + n) = v;
        }
    }
}

// ---------------------------------------------------------------------------
extern "C" void kernel_launch(void* const* d_in, const int* in_sizes, int n_in,
                              void* d_out, int out_size)
{
    (void)in_sizes; (void)n_in;

    const float* hs = (const float*)d_in[0];
    const float* Wq = (const float*)d_in[1];
    const float* bq = (const float*)d_in[2];
    const float* Wk = (const float*)d_in[3];
    const float* bk = (const float*)d_in[4];
    const float* Wv = (const float*)d_in[5];
    const float* bv = (const float*)d_in[6];
    const float* Wo = (const float*)d_in[7];
    const float* bo = (const float*)d_in[8];
    float* out = (float*)d_out;

    // probs live in the output buffer (flattened tuple: out then probs);
    // fall back to device scratch if the harness buffer only holds `out`.
    float* probs;
    if ((long long)out_size >= OUT_ELEMS + PROBS_ELEMS) {
        probs = out + OUT_ELEMS;
    } else {
        void* p = nullptr;
        cudaGetSymbolAddress(&p, g_probs_fallback);
        probs = (float*)p;
    }

    const dim3 gProj(H_ / 128, M_ / 128);           // (8, 64)
    proj_qkv_kernel<<<gProj, 256>>>(hs, Wq, bq, 0);
    proj_qkv_kernel<<<gProj, 256>>>(hs, Wk, bk, 1);
    proj_qkv_kernel<<<gProj, 256>>>(hs, Wv, bv, 2);

    scores_kernel<<<dim3(S_ / 128, S_ / 128, BH_), 256>>>(probs);   // (16,16,64)
    softmax_kernel<<<dim3(S_, BH_), 256>>>(probs);                  // (2048,64)
    ctx_kernel<<<dim3(S_ / 128, BH_), 128>>>(probs);                // (16,64)
    outproj_kernel<<<gProj, 256>>>(Wo, bo, hs, out);
}

// round 10
// speedup vs baseline: 1.4911x; 1.4904x over previous
#include <cuda_runtime.h>

// ---------------------------------------------------------------------------
// AttentionBlock (fp32 MHA): pproc(x,W,b) == x@W.T + b exactly in fwd pass.
// B=4, S=2048, H=1024, NH=16, HD=64. No scaling, no mask.
// Output buffer = [out (B,S,H)] ++ [probs (B,NH,S,S)], fp32.
//
// R9 version: double-buffered software-pipelined FFMA2 GEMMs (1 sync/iter,
// global prefetch overlapped with compute), softmax fused away:
//   scores writes exp(s-12) + deterministic partial row sums,
//   tiny kernel produces 1/rowsum,
//   ctx normalizes P at load time and writes normalized probs back in place.
// ---------------------------------------------------------------------------

namespace {
constexpr int B_  = 4;
constexpr int S_  = 2048;
constexpr int H_  = 1024;
constexpr int NH_ = 16;
constexpr int HD_ = 64;
constexpr int M_  = B_ * S_;          // 8192
constexpr int BH_ = B_ * NH_;         // 64
constexpr long long OUT_ELEMS   = (long long)M_ * H_;
constexpr long long PROBS_ELEMS = (long long)BH_ * S_ * S_;
}

// Scratch (device globals)
__device__ float g_q[M_ * H_];            // [BH][S][HD]
__device__ float g_k[M_ * H_];
__device__ float g_v[M_ * H_];
__device__ float g_ctx[M_ * H_];          // [B,S,H]
__device__ float g_psum[(long long)BH_ * S_ * 16];   // per-(row, n-tile) exp sums
__device__ float g_inv[BH_ * S_];         // 1 / row sum
__device__ float g_probs_fallback[268435456];

// ---------------- packed f32x2 FMA helpers --------------------------------
typedef unsigned long long u64;

__device__ __forceinline__ u64 pk2(float lo, float hi) {
    u64 r;
    asm("mov.b64 %0, {%1, %2};" : "=l"(r) : "f"(lo), "f"(hi));
    return r;
}
__device__ __forceinline__ void fma2(u64& d, u64 a, u64 b) {
    asm("fma.rn.f32x2 %0, %1, %2, %0;" : "+l"(d) : "l"(a), "l"(b));
}
__device__ __forceinline__ float2 up2(u64 v) {
    float2 r;
    asm("mov.b64 {%0, %1}, %2;" : "=f"(r.x), "=f"(r.y) : "l"(v));
    return r;
}

// ---------------------------------------------------------------------------
// Kernel 1: fused QKV projections (grid.z selects Q/K/V).
// C[m,n] = sum_k X[m,k] W[n,k] + bias[n], written as [BH][S][HD].
// 128x128 tile, BK=16, 256 threads, 8x8 per thread (cols n = p*32 + tx*2).
// ---------------------------------------------------------------------------
__global__ void __launch_bounds__(256, 2) proj_qkv_kernel(
    const float* __restrict__ X,
    const float* __restrict__ Wq, const float* __restrict__ Bq,
    const float* __restrict__ Wk, const float* __restrict__ Bk,
    const float* __restrict__ Wv, const float* __restrict__ Bv)
{
    const int sel = blockIdx.z;
    const float* W    = (sel == 0) ? Wq : (sel == 1) ? Wk : Wv;
    const float* bias = (sel == 0) ? Bq : (sel == 1) ? Bk : Bv;
    float* out        = (sel == 0) ? g_q : (sel == 1) ? g_k : g_v;

    constexpr int LDA = 132;
    __shared__ __align__(16) float As[2][16 * LDA];
    __shared__ __align__(16) float Bs[2][16 * LDA];

    const int tid = threadIdx.x;
    const int n0 = blockIdx.x * 128;
    const int m0 = blockIdx.y * 128;
    const int tx = tid & 15;
    const int ty = tid >> 4;
    const int lrow = tid >> 2;          // 0..63
    const int c4 = (tid & 3) * 4;

    const float* xA0 = X + (size_t)(m0 + lrow) * H_ + c4;
    const float* xA1 = xA0 + (size_t)64 * H_;
    const float* xB0 = W + (size_t)(n0 + lrow) * H_ + c4;
    const float* xB1 = xB0 + (size_t)64 * H_;

    u64 acc[8][4];
#pragma unroll
    for (int i = 0; i < 8; i++)
#pragma unroll
        for (int p = 0; p < 4; p++) acc[i][p] = 0ULL;

    float4 a0s = *(const float4*)(xA0);
    float4 a1s = *(const float4*)(xA1);
    float4 b0s = *(const float4*)(xB0);
    float4 b1s = *(const float4*)(xB1);

#define PROJ_STORE(BUF) do {                                               \
    float* as = &As[BUF][0]; float* bs = &Bs[BUF][0];                      \
    as[(c4+0)*LDA + lrow]      = a0s.x; as[(c4+1)*LDA + lrow]      = a0s.y;\
    as[(c4+2)*LDA + lrow]      = a0s.z; as[(c4+3)*LDA + lrow]      = a0s.w;\
    as[(c4+0)*LDA + lrow + 64] = a1s.x; as[(c4+1)*LDA + lrow + 64] = a1s.y;\
    as[(c4+2)*LDA + lrow + 64] = a1s.z; as[(c4+3)*LDA + lrow + 64] = a1s.w;\
    bs[(c4+0)*LDA + lrow]      = b0s.x; bs[(c4+1)*LDA + lrow]      = b0s.y;\
    bs[(c4+2)*LDA + lrow]      = b0s.z; bs[(c4+3)*LDA + lrow]      = b0s.w;\
    bs[(c4+0)*LDA + lrow + 64] = b1s.x; bs[(c4+1)*LDA + lrow + 64] = b1s.y;\
    bs[(c4+2)*LDA + lrow + 64] = b1s.z; bs[(c4+3)*LDA + lrow + 64] = b1s.w;\
} while (0)

    PROJ_STORE(0);
    __syncthreads();

    for (int it = 0; it < 64; it++) {
        const int buf = it & 1;
        if (it < 63) {
            const int k0 = (it + 1) * 16;
            a0s = *(const float4*)(xA0 + k0);
            a1s = *(const float4*)(xA1 + k0);
            b0s = *(const float4*)(xB0 + k0);
            b1s = *(const float4*)(xB1 + k0);
        }
#pragma unroll
        for (int kk = 0; kk < 16; kk++) {
            const float* as = &As[buf][kk * LDA];
            const float* bs = &Bs[buf][kk * LDA];
            float4 a0 = *(const float4*)(as + ty * 8);
            float4 a1 = *(const float4*)(as + ty * 8 + 4);
            u64 ad[8];
            ad[0] = pk2(a0.x, a0.x); ad[1] = pk2(a0.y, a0.y);
            ad[2] = pk2(a0.z, a0.z); ad[3] = pk2(a0.w, a0.w);
            ad[4] = pk2(a1.x, a1.x); ad[5] = pk2(a1.y, a1.y);
            ad[6] = pk2(a1.z, a1.z); ad[7] = pk2(a1.w, a1.w);
            u64 b0 = *(const u64*)(bs + 0 * 32 + tx * 2);
            u64 b1 = *(const u64*)(bs + 1 * 32 + tx * 2);
            u64 b2 = *(const u64*)(bs + 2 * 32 + tx * 2);
            u64 b3 = *(const u64*)(bs + 3 * 32 + tx * 2);
#pragma unroll
            for (int i = 0; i < 8; i++) {
                fma2(acc[i][0], ad[i], b0);
                fma2(acc[i][1], ad[i], b1);
                fma2(acc[i][2], ad[i], b2);
                fma2(acc[i][3], ad[i], b3);
            }
        }
        if (it < 63) PROJ_STORE(buf ^ 1);
        __syncthreads();
    }

#pragma unroll
    for (int i = 0; i < 8; i++) {
        const int m = m0 + ty * 8 + i;
        const int b = m >> 11;
        const int s = m & (S_ - 1);
#pragma unroll
        for (int p = 0; p < 4; p++) {
            float2 v = up2(acc[i][p]);
            const int n = n0 + p * 32 + tx * 2;
            float2 bb = *(const float2*)(bias + n);
            v.x += bb.x; v.y += bb.y;
            const int h = n >> 6, d = n & 63;
            *(float2*)(out + ((size_t)((b * NH_ + h) * S_ + s)) * HD_ + d) = v;
        }
    }
#undef PROJ_STORE
}

// ---------------------------------------------------------------------------
// Kernel 2: scores per (b,h): exp(Q K^T - 12) -> probs (unnormalized) plus
// deterministic per-(row, n-tile) partial sums.
// ---------------------------------------------------------------------------
__global__ void __launch_bounds__(256, 2) scores_kernel(float* __restrict__ probs)
{
    constexpr int LDA = 132;
    __shared__ __align__(16) float As[2][16 * LDA];
    __shared__ __align__(16) float Bs[2][16 * LDA];

    const int tid = threadIdx.x;
    const int n0 = blockIdx.x * 128;
    const int m0 = blockIdx.y * 128;
    const int bh = blockIdx.z;
    const float* Q = g_q + (size_t)bh * S_ * HD_;
    const float* K = g_k + (size_t)bh * S_ * HD_;

    const int tx = tid & 15;
    const int ty = tid >> 4;
    const int lrow = tid >> 2;
    const int c4 = (tid & 3) * 4;

    const float* xA0 = Q + (size_t)(m0 + lrow) * HD_ + c4;
    const float* xA1 = xA0 + (size_t)64 * HD_;
    const float* xB0 = K + (size_t)(n0 + lrow) * HD_ + c4;
    const float* xB1 = xB0 + (size_t)64 * HD_;

    u64 acc[8][4];
#pragma unroll
    for (int i = 0; i < 8; i++)
#pragma unroll
        for (int p = 0; p < 4; p++) acc[i][p] = 0ULL;

    float4 a0s = *(const float4*)(xA0);
    float4 a1s = *(const float4*)(xA1);
    float4 b0s = *(const float4*)(xB0);
    float4 b1s = *(const float4*)(xB1);

#define SC_STORE(BUF) do {                                                 \
    float* as = &As[BUF][0]; float* bs = &Bs[BUF][0];                      \
    as[(c4+0)*LDA + lrow]      = a0s.x; as[(c4+1)*LDA + lrow]      = a0s.y;\
    as[(c4+2)*LDA + lrow]      = a0s.z; as[(c4+3)*LDA + lrow]      = a0s.w;\
    as[(c4+0)*LDA + lrow + 64] = a1s.x; as[(c4+1)*LDA + lrow + 64] = a1s.y;\
    as[(c4+2)*LDA + lrow + 64] = a1s.z; as[(c4+3)*LDA + lrow + 64] = a1s.w;\
    bs[(c4+0)*LDA + lrow]      = b0s.x; bs[(c4+1)*LDA + lrow]      = b0s.y;\
    bs[(c4+2)*LDA + lrow]      = b0s.z; bs[(c4+3)*LDA + lrow]      = b0s.w;\
    bs[(c4+0)*LDA + lrow + 64] = b1s.x; bs[(c4+1)*LDA + lrow + 64] = b1s.y;\
    bs[(c4+2)*LDA + lrow + 64] = b1s.z; bs[(c4+3)*LDA + lrow + 64] = b1s.w;\
} while (0)

    SC_STORE(0);
    __syncthreads();

    for (int it = 0; it < 4; it++) {
        const int buf = it & 1;
        if (it < 3) {
            const int k0 = (it + 1) * 16;
            a0s = *(const float4*)(xA0 + k0);
            a1s = *(const float4*)(xA1 + k0);
            b0s = *(const float4*)(xB0 + k0);
            b1s = *(const float4*)(xB1 + k0);
        }
#pragma unroll
        for (int kk = 0; kk < 16; kk++) {
            const float* as = &As[buf][kk * LDA];
            const float* bs = &Bs[buf][kk * LDA];
            float4 a0 = *(const float4*)(as + ty * 8);
            float4 a1 = *(const float4*)(as + ty * 8 + 4);
            u64 ad[8];
            ad[0] = pk2(a0.x, a0.x); ad[1] = pk2(a0.y, a0.y);
            ad[2] = pk2(a0.z, a0.z); ad[3] = pk2(a0.w, a0.w);
            ad[4] = pk2(a1.x, a1.x); ad[5] = pk2(a1.y, a1.y);
            ad[6] = pk2(a1.z, a1.z); ad[7] = pk2(a1.w, a1.w);
            u64 b0 = *(const u64*)(bs + 0 * 32 + tx * 2);
            u64 b1 = *(const u64*)(bs + 1 * 32 + tx * 2);
            u64 b2 = *(const u64*)(bs + 2 * 32 + tx * 2);
            u64 b3 = *(const u64*)(bs + 3 * 32 + tx * 2);
#pragma unroll
            for (int i = 0; i < 8; i++) {
                fma2(acc[i][0], ad[i], b0);
                fma2(acc[i][1], ad[i], b1);
                fma2(acc[i][2], ad[i], b2);
                fma2(acc[i][3], ad[i], b3);
            }
        }
        if (it < 3) SC_STORE(buf ^ 1);
        __syncthreads();
    }

    // epilogue: exp(s - 12), store unnormalized, partial row sums
    float* P = probs + (size_t)bh * S_ * S_;
#pragma unroll
    for (int i = 0; i < 8; i++) {
        const int m = m0 + ty * 8 + i;
        float rs = 0.f;
#pragma unroll
        for (int p = 0; p < 4; p++) {
            float2 v = up2(acc[i][p]);
            v.x = __expf(v.x - 12.0f);
            v.y = __expf(v.y - 12.0f);
            rs += v.x + v.y;
            *(float2*)(P + (size_t)m * S_ + n0 + p * 32 + tx * 2) = v;
        }
        // reduce across the 16 tx lanes (xor offsets stay within 16-lane group)
#pragma unroll
        for (int o = 8; o; o >>= 1) rs += __shfl_xor_sync(0xffffffffu, rs, o);
        if (tx == 0)
            g_psum[((size_t)bh * S_ + m) * 16 + blockIdx.x] = rs;
    }
#undef SC_STORE
}

// ---------------------------------------------------------------------------
// Kernel 3: 1/rowsum (deterministic, 16 partials per row).
// ---------------------------------------------------------------------------
__global__ void __launch_bounds__(256) rsum_kernel()
{
    const int r = blockIdx.x * 256 + threadIdx.x;   // < 131072
    const float4* p = (const float4*)(g_psum + (size_t)r * 16);
    float4 a = p[0], b = p[1], c = p[2], d = p[3];
    float s = ((a.x + a.y) + (a.z + a.w)) + ((b.x + b.y) + (b.z + b.w))
            + ((c.x + c.y) + (c.z + c.w)) + ((d.x + d.y) + (d.z + d.w));
    g_inv[r] = 1.0f / s;
}

// ---------------------------------------------------------------------------
// Kernel 4: ctx = P_norm @ V per (b,h); P is normalized at load time and the
// normalized probs are written back in place. Tile 256x64, BK=16, 256 thr.
// ---------------------------------------------------------------------------
__global__ void __launch_bounds__(256, 2) ctx_kernel(float* __restrict__ probs)
{
    constexpr int LDA = 260;
    constexpr int LDB = 68;
    __shared__ __align__(16) float As[2][16 * LDA];
    __shared__ __align__(16) float Bs[2][16 * LDB];

    const int tid = threadIdx.x;
    const int tx = tid & 7;
    const int ty = tid >> 3;
    const int m0 = blockIdx.x * 256;
    const int bh = blockIdx.y;
    float* P = probs + (size_t)bh * S_ * S_;
    const float* V = g_v + (size_t)bh * S_ * HD_;

    const int lrow = tid >> 2;          // 0..63
    const int c4 = (tid & 3) * 4;

    float iv[4];
    float* pA[4];
#pragma unroll
    for (int t = 0; t < 4; t++) {
        const int r = m0 + lrow + t * 64;
        iv[t] = g_inv[bh * S_ + r];
        pA[t] = P + (size_t)r * S_ + c4;
    }
    const int jr = tid >> 4;
    const int dc = (tid & 15) * 4;
    const float* pB = V + (size_t)jr * HD_ + dc;

    u64 acc[8][4];
#pragma unroll
    for (int i = 0; i < 8; i++)
#pragma unroll
        for (int p = 0; p < 4; p++) acc[i][p] = 0ULL;

    float4 a_s[4];
    float4 b_s;
#pragma unroll
    for (int t = 0; t < 4; t++) {
        float4 v = *(const float4*)(pA[t]);
        v.x *= iv[t]; v.y *= iv[t]; v.z *= iv[t]; v.w *= iv[t];
        *(float4*)(pA[t]) = v;          // write back normalized probs
        a_s[t] = v;
    }
    b_s = *(const float4*)(pB);

#define CTX_STORE(BUF) do {                                                \
    float* as = &As[BUF][0];                                               \
    _Pragma("unroll")                                                      \
    for (int t = 0; t < 4; t++) {                                          \
        as[(c4+0)*LDA + lrow + t*64] = a_s[t].x;                           \
        as[(c4+1)*LDA + lrow + t*64] = a_s[t].y;                           \
        as[(c4+2)*LDA + lrow + t*64] = a_s[t].z;                           \
        as[(c4+3)*LDA + lrow + t*64] = a_s[t].w;                           \
    }                                                                      \
    *(float4*)(&Bs[BUF][jr * LDB + dc]) = b_s;                             \
} while (0)

    CTX_STORE(0);
    __syncthreads();

    for (int it = 0; it < 128; it++) {
        const int buf = it & 1;
        if (it < 127) {
            const int k0 = (it + 1) * 16;
#pragma unroll
            for (int t = 0; t < 4; t++) {
                float4 v = *(const float4*)(pA[t] + k0);
                v.x *= iv[t]; v.y *= iv[t]; v.z *= iv[t]; v.w *= iv[t];
                *(float4*)(pA[t] + k0) = v;
                a_s[t] = v;
            }
            b_s = *(const float4*)(pB + (size_t)k0 * HD_);
        }
#pragma unroll
        for (int kk = 0; kk < 16; kk++) {
            const float* as = &As[buf][kk * LDA];
            const float* bs = &Bs[buf][kk * LDB];
            float4 a0 = *(const float4*)(as + ty * 8);
            float4 a1 = *(const float4*)(as + ty * 8 + 4);
            u64 ad[8];
            ad[0] = pk2(a0.x, a0.x); ad[1] = pk2(a0.y, a0.y);
            ad[2] = pk2(a0.z, a0.z); ad[3] = pk2(a0.w, a0.w);
            ad[4] = pk2(a1.x, a1.x); ad[5] = pk2(a1.y, a1.y);
            ad[6] = pk2(a1.z, a1.z); ad[7] = pk2(a1.w, a1.w);
            u64 b0 = *(const u64*)(bs + 0 * 16 + tx * 2);
            u64 b1 = *(const u64*)(bs + 1 * 16 + tx * 2);
            u64 b2 = *(const u64*)(bs + 2 * 16 + tx * 2);
            u64 b3 = *(const u64*)(bs + 3 * 16 + tx * 2);
#pragma unroll
            for (int i = 0; i < 8; i++) {
                fma2(acc[i][0], ad[i], b0);
                fma2(acc[i][1], ad[i], b1);
                fma2(acc[i][2], ad[i], b2);
                fma2(acc[i][3], ad[i], b3);
            }
        }
        if (it < 127) CTX_STORE(buf ^ 1);
        __syncthreads();
    }

    const int b = bh >> 4;
    const int h = bh & 15;
#pragma unroll
    for (int i = 0; i < 8; i++) {
        const int s = m0 + ty * 8 + i;
#pragma unroll
        for (int p = 0; p < 4; p++) {
            float2 v = up2(acc[i][p]);
            const int d = p * 16 + tx * 2;
            *(float2*)(g_ctx + ((size_t)(b * S_ + s)) * H_ + h * HD_ + d) = v;
        }
    }
#undef CTX_STORE
}

// ---------------------------------------------------------------------------
// Kernel 5: out[m,n] = sum_k ctx[m,k] Wo[n,k] + bo[n] + hidden[m,n]
// ---------------------------------------------------------------------------
__global__ void __launch_bounds__(256, 2) outproj_kernel(
    const float* __restrict__ W,
    const float* __restrict__ bias,
    const float* __restrict__ hid,
    float* __restrict__ out)
{
    constexpr int LDA = 132;
    __shared__ __align__(16) float As[2][16 * LDA];
    __shared__ __align__(16) float Bs[2][16 * LDA];

    const int tid = threadIdx.x;
    const int n0 = blockIdx.x * 128;
    const int m0 = blockIdx.y * 128;
    const int tx = tid & 15;
    const int ty = tid >> 4;
    const int lrow = tid >> 2;
    const int c4 = (tid & 3) * 4;

    const float* xA0 = g_ctx + (size_t)(m0 + lrow) * H_ + c4;
    const float* xA1 = xA0 + (size_t)64 * H_;
    const float* xB0 = W + (size_t)(n0 + lrow) * H_ + c4;
    const float* xB1 = xB0 + (size_t)64 * H_;

    u64 acc[8][4];
#pragma unroll
    for (int i = 0; i < 8; i++)
#pragma unroll
        for (int p = 0; p < 4; p++) acc[i][p] = 0ULL;

    float4 a0s = *(const float4*)(xA0);
    float4 a1s = *(const float4*)(xA1);
    float4 b0s = *(const float4*)(xB0);
    float4 b1s = *(const float4*)(xB1);

#define OP_STORE(BUF) do {                                                 \
    float* as = &As[BUF][0]; float* bs = &Bs[BUF][0];                      \
    as[(c4+0)*LDA + lrow]      = a0s.x; as[(c4+1)*LDA + lrow]      = a0s.y;\
    as[(c4+2)*LDA + lrow]      = a0s.z; as[(c4+3)*LDA + lrow]      = a0s.w;\
    as[(c4+0)*LDA + lrow + 64] = a1s.x; as[(c4+1)*LDA + lrow + 64] = a1s.y;\
    as[(c4+2)*LDA + lrow + 64] = a1s.z; as[(c4+3)*LDA + lrow + 64] = a1s.w;\
    bs[(c4+0)*LDA + lrow]      = b0s.x; bs[(c4+1)*LDA + lrow]      = b0s.y;\
    bs[(c4+2)*LDA + lrow]      = b0s.z; bs[(c4+3)*LDA + lrow]      = b0s.w;\
    bs[(c4+0)*LDA + lrow + 64] = b1s.x; bs[(c4+1)*LDA + lrow + 64] = b1s.y;\
    bs[(c4+2)*LDA + lrow + 64] = b1s.z; bs[(c4+3)*LDA + lrow + 64] = b1s.w;\
} while (0)

    OP_STORE(0);
    __syncthreads();

    for (int it = 0; it < 64; it++) {
        const int buf = it & 1;
        if (it < 63) {
            const int k0 = (it + 1) * 16;
            a0s = *(const float4*)(xA0 + k0);
            a1s = *(const float4*)(xA1 + k0);
            b0s = *(const float4*)(xB0 + k0);
            b1s = *(const float4*)(xB1 + k0);
        }
#pragma unroll
        for (int kk = 0; kk < 16; kk++) {
            const float* as = &As[buf][kk * LDA];
            const float* bs = &Bs[buf][kk * LDA];
            float4 a0 = *(const float4*)(as + ty * 8);
            float4 a1 = *(const float4*)(as + ty * 8 + 4);
            u64 ad[8];
            ad[0] = pk2(a0.x, a0.x); ad[1] = pk2(a0.y, a0.y);
            ad[2] = pk2(a0.z, a0.z); ad[3] = pk2(a0.w, a0.w);
            ad[4] = pk2(a1.x, a1.x); ad[5] = pk2(a1.y, a1.y);
            ad[6] = pk2(a1.z, a1.z); ad[7] = pk2(a1.w, a1.w);
            u64 b0 = *(const u64*)(bs + 0 * 32 + tx * 2);
            u64 b1 = *(const u64*)(bs + 1 * 32 + tx * 2);
            u64 b2 = *(const u64*)(bs + 2 * 32 + tx * 2);
            u64 b3 = *(const u64*)(bs + 3 * 32 + tx * 2);
#pragma unroll
            for (int i = 0; i < 8; i++) {
                fma2(acc[i][0], ad[i], b0);
                fma2(acc[i][1], ad[i], b1);
                fma2(acc[i][2], ad[i], b2);
                fma2(acc[i][3], ad[i], b3);
            }
        }
        if (it < 63) OP_STORE(buf ^ 1);
        __syncthreads();
    }

#pragma unroll
    for (int i = 0; i < 8; i++) {
        const int m = m0 + ty * 8 + i;
#pragma unroll
        for (int p = 0; p < 4; p++) {
            float2 v = up2(acc[i][p]);
            const int n = n0 + p * 32 + tx * 2;
            float2 bb = *(const float2*)(bias + n);
            float2 hh = *(const float2*)(hid + (size_t)m * H_ + n);
            v.x += bb.x + hh.x;
            v.y += bb.y + hh.y;
            *(float2*)(out + (size_t)m * H_ + n) = v;
        }
    }
#undef OP_STORE
}

// ---------------------------------------------------------------------------
extern "C" void kernel_launch(void* const* d_in, const int* in_sizes, int n_in,
                              void* d_out, int out_size)
{
    (void)in_sizes; (void)n_in;

    const float* hs = (const float*)d_in[0];
    const float* Wq = (const float*)d_in[1];
    const float* bq = (const float*)d_in[2];
    const float* Wk = (const float*)d_in[3];
    const float* bk = (const float*)d_in[4];
    const float* Wv = (const float*)d_in[5];
    const float* bv = (const float*)d_in[6];
    const float* Wo = (const float*)d_in[7];
    const float* bo = (const float*)d_in[8];
    float* out = (float*)d_out;

    float* probs;
    if ((long long)out_size >= OUT_ELEMS + PROBS_ELEMS) {
        probs = out + OUT_ELEMS;
    } else {
        void* p = nullptr;
        cudaGetSymbolAddress(&p, g_probs_fallback);
        probs = (float*)p;
    }

    proj_qkv_kernel<<<dim3(H_ / 128, M_ / 128, 3), 256>>>(hs, Wq, bq, Wk, bk, Wv, bv);
    scores_kernel<<<dim3(S_ / 128, S_ / 128, BH_), 256>>>(probs);
    rsum_kernel<<<(BH_ * S_) / 256, 256>>>();
    ctx_kernel<<<dim3(S_ / 256, BH_), 256>>>(probs);
    outproj_kernel<<<dim3(H_ / 128, M_ / 128), 256>>>(Wo, bo, hs, out);
}

// round 11
// speedup vs baseline: 1.4923x; 1.0008x over previous
#include <cuda_runtime.h>

// ---------------------------------------------------------------------------
// AttentionBlock (fp32 MHA): pproc(x,W,b) == x@W.T + b exactly in fwd pass.
// B=4, S=2048, H=1024, NH=16, HD=64. No scaling, no mask.
// Output buffer = [out (B,S,H)] ++ [probs (B,NH,S,S)], fp32.
//
// R9 version: double-buffered software-pipelined FFMA2 GEMMs (1 sync/iter,
// global prefetch overlapped with compute), softmax fused away:
//   scores writes exp(s-12) + deterministic partial row sums,
//   tiny kernel produces 1/rowsum,
//   ctx normalizes P at load time and writes normalized probs back in place.
// ---------------------------------------------------------------------------

namespace {
constexpr int B_  = 4;
constexpr int S_  = 2048;
constexpr int H_  = 1024;
constexpr int NH_ = 16;
constexpr int HD_ = 64;
constexpr int M_  = B_ * S_;          // 8192
constexpr int BH_ = B_ * NH_;         // 64
constexpr long long OUT_ELEMS   = (long long)M_ * H_;
constexpr long long PROBS_ELEMS = (long long)BH_ * S_ * S_;
}

// Scratch (device globals)
__device__ float g_q[M_ * H_];            // [BH][S][HD]
__device__ float g_k[M_ * H_];
__device__ float g_v[M_ * H_];
__device__ float g_ctx[M_ * H_];          // [B,S,H]
__device__ float g_psum[(long long)BH_ * S_ * 16];   // per-(row, n-tile) exp sums
__device__ float g_inv[BH_ * S_];         // 1 / row sum
__device__ float g_probs_fallback[268435456];

// ---------------- packed f32x2 FMA helpers --------------------------------
typedef unsigned long long u64;

__device__ __forceinline__ u64 pk2(float lo, float hi) {
    u64 r;
    asm("mov.b64 %0, {%1, %2};" : "=l"(r) : "f"(lo), "f"(hi));
    return r;
}
__device__ __forceinline__ void fma2(u64& d, u64 a, u64 b) {
    asm("fma.rn.f32x2 %0, %1, %2, %0;" : "+l"(d) : "l"(a), "l"(b));
}
__device__ __forceinline__ float2 up2(u64 v) {
    float2 r;
    asm("mov.b64 {%0, %1}, %2;" : "=f"(r.x), "=f"(r.y) : "l"(v));
    return r;
}

// ---------------------------------------------------------------------------
// Kernel 1: fused QKV projections (grid.z selects Q/K/V).
// C[m,n] = sum_k X[m,k] W[n,k] + bias[n], written as [BH][S][HD].
// 128x128 tile, BK=16, 256 threads, 8x8 per thread (cols n = p*32 + tx*2).
// ---------------------------------------------------------------------------
__global__ void __launch_bounds__(256, 2) proj_qkv_kernel(
    const float* __restrict__ X,
    const float* __restrict__ Wq, const float* __restrict__ Bq,
    const float* __restrict__ Wk, const float* __restrict__ Bk,
    const float* __restrict__ Wv, const float* __restrict__ Bv)
{
    const int sel = blockIdx.z;
    const float* W    = (sel == 0) ? Wq : (sel == 1) ? Wk : Wv;
    const float* bias = (sel == 0) ? Bq : (sel == 1) ? Bk : Bv;
    float* out        = (sel == 0) ? g_q : (sel == 1) ? g_k : g_v;

    constexpr int LDA = 132;
    __shared__ __align__(16) float As[2][16 * LDA];
    __shared__ __align__(16) float Bs[2][16 * LDA];

    const int tid = threadIdx.x;
    const int n0 = blockIdx.x * 128;
    const int m0 = blockIdx.y * 128;
    const int tx = tid & 15;
    const int ty = tid >> 4;
    const int lrow = tid >> 2;          // 0..63
    const int c4 = (tid & 3) * 4;

    const float* xA0 = X + (size_t)(m0 + lrow) * H_ + c4;
    const float* xA1 = xA0 + (size_t)64 * H_;
    const float* xB0 = W + (size_t)(n0 + lrow) * H_ + c4;
    const float* xB1 = xB0 + (size_t)64 * H_;

    u64 acc[8][4];
#pragma unroll
    for (int i = 0; i < 8; i++)
#pragma unroll
        for (int p = 0; p < 4; p++) acc[i][p] = 0ULL;

    float4 a0s = *(const float4*)(xA0);
    float4 a1s = *(const float4*)(xA1);
    float4 b0s = *(const float4*)(xB0);
    float4 b1s = *(const float4*)(xB1);

#define PROJ_STORE(BUF) do {                                               \
    float* as = &As[BUF][0]; float* bs = &Bs[BUF][0];                      \
    as[(c4+0)*LDA + lrow]      = a0s.x; as[(c4+1)*LDA + lrow]      = a0s.y;\
    as[(c4+2)*LDA + lrow]      = a0s.z; as[(c4+3)*LDA + lrow]      = a0s.w;\
    as[(c4+0)*LDA + lrow + 64] = a1s.x; as[(c4+1)*LDA + lrow + 64] = a1s.y;\
    as[(c4+2)*LDA + lrow + 64] = a1s.z; as[(c4+3)*LDA + lrow + 64] = a1s.w;\
    bs[(c4+0)*LDA + lrow]      = b0s.x; bs[(c4+1)*LDA + lrow]      = b0s.y;\
    bs[(c4+2)*LDA + lrow]      = b0s.z; bs[(c4+3)*LDA + lrow]      = b0s.w;\
    bs[(c4+0)*LDA + lrow + 64] = b1s.x; bs[(c4+1)*LDA + lrow + 64] = b1s.y;\
    bs[(c4+2)*LDA + lrow + 64] = b1s.z; bs[(c4+3)*LDA + lrow + 64] = b1s.w;\
} while (0)

    PROJ_STORE(0);
    __syncthreads();

    for (int it = 0; it < 64; it++) {
        const int buf = it & 1;
        if (it < 63) {
            const int k0 = (it + 1) * 16;
            a0s = *(const float4*)(xA0 + k0);
            a1s = *(const float4*)(xA1 + k0);
            b0s = *(const float4*)(xB0 + k0);
            b1s = *(const float4*)(xB1 + k0);
        }
#pragma unroll
        for (int kk = 0; kk < 16; kk++) {
            const float* as = &As[buf][kk * LDA];
            const float* bs = &Bs[buf][kk * LDA];
            float4 a0 = *(const float4*)(as + ty * 8);
            float4 a1 = *(const float4*)(as + ty * 8 + 4);
            u64 ad[8];
            ad[0] = pk2(a0.x, a0.x); ad[1] = pk2(a0.y, a0.y);
            ad[2] = pk2(a0.z, a0.z); ad[3] = pk2(a0.w, a0.w);
            ad[4] = pk2(a1.x, a1.x); ad[5] = pk2(a1.y, a1.y);
            ad[6] = pk2(a1.z, a1.z); ad[7] = pk2(a1.w, a1.w);
            u64 b0 = *(const u64*)(bs + 0 * 32 + tx * 2);
            u64 b1 = *(const u64*)(bs + 1 * 32 + tx * 2);
            u64 b2 = *(const u64*)(bs + 2 * 32 + tx * 2);
            u64 b3 = *(const u64*)(bs + 3 * 32 + tx * 2);
#pragma unroll
            for (int i = 0; i < 8; i++) {
                fma2(acc[i][0], ad[i], b0);
                fma2(acc[i][1], ad[i], b1);
                fma2(acc[i][2], ad[i], b2);
                fma2(acc[i][3], ad[i], b3);
            }
        }
        if (it < 63) PROJ_STORE(buf ^ 1);
        __syncthreads();
    }

#pragma unroll
    for (int i = 0; i < 8; i++) {
        const int m = m0 + ty * 8 + i;
        const int b = m >> 11;
        const int s = m & (S_ - 1);
#pragma unroll
        for (int p = 0; p < 4; p++) {
            float2 v = up2(acc[i][p]);
            const int n = n0 + p * 32 + tx * 2;
            float2 bb = *(const float2*)(bias + n);
            v.x += bb.x; v.y += bb.y;
            const int h = n >> 6, d = n & 63;
            *(float2*)(out + ((size_t)((b * NH_ + h) * S_ + s)) * HD_ + d) = v;
        }
    }
#undef PROJ_STORE
}

// ---------------------------------------------------------------------------
// Kernel 2: scores per (b,h): exp(Q K^T - 12) -> probs (unnormalized) plus
// deterministic per-(row, n-tile) partial sums.
// ---------------------------------------------------------------------------
__global__ void __launch_bounds__(256, 2) scores_kernel(float* __restrict__ probs)
{
    constexpr int LDA = 132;
    __shared__ __align__(16) float As[2][16 * LDA];
    __shared__ __align__(16) float Bs[2][16 * LDA];

    const int tid = threadIdx.x;
    const int n0 = blockIdx.x * 128;
    const int m0 = blockIdx.y * 128;
    const int bh = blockIdx.z;
    const float* Q = g_q + (size_t)bh * S_ * HD_;
    const float* K = g_k + (size_t)bh * S_ * HD_;

    const int tx = tid & 15;
    const int ty = tid >> 4;
    const int lrow = tid >> 2;
    const int c4 = (tid & 3) * 4;

    const float* xA0 = Q + (size_t)(m0 + lrow) * HD_ + c4;
    const float* xA1 = xA0 + (size_t)64 * HD_;
    const float* xB0 = K + (size_t)(n0 + lrow) * HD_ + c4;
    const float* xB1 = xB0 + (size_t)64 * HD_;

    u64 acc[8][4];
#pragma unroll
    for (int i = 0; i < 8; i++)
#pragma unroll
        for (int p = 0; p < 4; p++) acc[i][p] = 0ULL;

    float4 a0s = *(const float4*)(xA0);
    float4 a1s = *(const float4*)(xA1);
    float4 b0s = *(const float4*)(xB0);
    float4 b1s = *(const float4*)(xB1);

#define SC_STORE(BUF) do {                                                 \
    float* as = &As[BUF][0]; float* bs = &Bs[BUF][0];                      \
    as[(c4+0)*LDA + lrow]      = a0s.x; as[(c4+1)*LDA + lrow]      = a0s.y;\
    as[(c4+2)*LDA + lrow]      = a0s.z; as[(c4+3)*LDA + lrow]      = a0s.w;\
    as[(c4+0)*LDA + lrow + 64] = a1s.x; as[(c4+1)*LDA + lrow + 64] = a1s.y;\
    as[(c4+2)*LDA + lrow + 64] = a1s.z; as[(c4+3)*LDA + lrow + 64] = a1s.w;\
    bs[(c4+0)*LDA + lrow]      = b0s.x; bs[(c4+1)*LDA + lrow]      = b0s.y;\
    bs[(c4+2)*LDA + lrow]      = b0s.z; bs[(c4+3)*LDA + lrow]      = b0s.w;\
    bs[(c4+0)*LDA + lrow + 64] = b1s.x; bs[(c4+1)*LDA + lrow + 64] = b1s.y;\
    bs[(c4+2)*LDA + lrow + 64] = b1s.z; bs[(c4+3)*LDA + lrow + 64] = b1s.w;\
} while (0)

    SC_STORE(0);
    __syncthreads();

    for (int it = 0; it < 4; it++) {
        const int buf = it & 1;
        if (it < 3) {
            const int k0 = (it + 1) * 16;
            a0s = *(const float4*)(xA0 + k0);
            a1s = *(const float4*)(xA1 + k0);
            b0s = *(const float4*)(xB0 + k0);
            b1s = *(const float4*)(xB1 + k0);
        }
#pragma unroll
        for (int kk = 0; kk < 16; kk++) {
            const float* as = &As[buf][kk * LDA];
            const float* bs = &Bs[buf][kk * LDA];
            float4 a0 = *(const float4*)(as + ty * 8);
            float4 a1 = *(const float4*)(as + ty * 8 + 4);
            u64 ad[8];
            ad[0] = pk2(a0.x, a0.x); ad[1] = pk2(a0.y, a0.y);
            ad[2] = pk2(a0.z, a0.z); ad[3] = pk2(a0.w, a0.w);
            ad[4] = pk2(a1.x, a1.x); ad[5] = pk2(a1.y, a1.y);
            ad[6] = pk2(a1.z, a1.z); ad[7] = pk2(a1.w, a1.w);
            u64 b0 = *(const u64*)(bs + 0 * 32 + tx * 2);
            u64 b1 = *(const u64*)(bs + 1 * 32 + tx * 2);
            u64 b2 = *(const u64*)(bs + 2 * 32 + tx * 2);
            u64 b3 = *(const u64*)(bs + 3 * 32 + tx * 2);
#pragma unroll
            for (int i = 0; i < 8; i++) {
                fma2(acc[i][0], ad[i], b0);
                fma2(acc[i][1], ad[i], b1);
                fma2(acc[i][2], ad[i], b2);
                fma2(acc[i][3], ad[i], b3);
            }
        }
        if (it < 3) SC_STORE(buf ^ 1);
        __syncthreads();
    }

    // epilogue: exp(s - 12), store unnormalized, partial row sums
    float* P = probs + (size_t)bh * S_ * S_;
#pragma unroll
    for (int i = 0; i < 8; i++) {
        const int m = m0 + ty * 8 + i;
        float rs = 0.f;
#pragma unroll
        for (int p = 0; p < 4; p++) {
            float2 v = up2(acc[i][p]);
            v.x = __expf(v.x - 12.0f);
            v.y = __expf(v.y - 12.0f);
            rs += v.x + v.y;
            *(float2*)(P + (size_t)m * S_ + n0 + p * 32 + tx * 2) = v;
        }
        // reduce across the 16 tx lanes (xor offsets stay within 16-lane group)
#pragma unroll
        for (int o = 8; o; o >>= 1) rs += __shfl_xor_sync(0xffffffffu, rs, o);
        if (tx == 0)
            g_psum[((size_t)bh * S_ + m) * 16 + blockIdx.x] = rs;
    }
#undef SC_STORE
}

// ---------------------------------------------------------------------------
// Kernel 3: 1/rowsum (deterministic, 16 partials per row).
// ---------------------------------------------------------------------------
__global__ void __launch_bounds__(256) rsum_kernel()
{
    const int r = blockIdx.x * 256 + threadIdx.x;   // < 131072
    const float4* p = (const float4*)(g_psum + (size_t)r * 16);
    float4 a = p[0], b = p[1], c = p[2], d = p[3];
    float s = ((a.x + a.y) + (a.z + a.w)) + ((b.x + b.y) + (b.z + b.w))
            + ((c.x + c.y) + (c.z + c.w)) + ((d.x + d.y) + (d.z + d.w));
    g_inv[r] = 1.0f / s;
}

// ---------------------------------------------------------------------------
// Kernel 4: ctx = P_norm @ V per (b,h); P is normalized at load time and the
// normalized probs are written back in place. Tile 256x64, BK=16, 256 thr.
// ---------------------------------------------------------------------------
__global__ void __launch_bounds__(256, 2) ctx_kernel(float* __restrict__ probs)
{
    constexpr int LDA = 260;
    constexpr int LDB = 68;
    __shared__ __align__(16) float As[2][16 * LDA];
    __shared__ __align__(16) float Bs[2][16 * LDB];

    const int tid = threadIdx.x;
    const int tx = tid & 7;
    const int ty = tid >> 3;
    const int m0 = blockIdx.x * 256;
    const int bh = blockIdx.y;
    float* P = probs + (size_t)bh * S_ * S_;
    const float* V = g_v + (size_t)bh * S_ * HD_;

    const int lrow = tid >> 2;          // 0..63
    const int c4 = (tid & 3) * 4;

    float iv[4];
    float* pA[4];
#pragma unroll
    for (int t = 0; t < 4; t++) {
        const int r = m0 + lrow + t * 64;
        iv[t] = g_inv[bh * S_ + r];
        pA[t] = P + (size_t)r * S_ + c4;
    }
    const int jr = tid >> 4;
    const int dc = (tid & 15) * 4;
    const float* pB = V + (size_t)jr * HD_ + dc;

    u64 acc[8][4];
#pragma unroll
    for (int i = 0; i < 8; i++)
#pragma unroll
        for (int p = 0; p < 4; p++) acc[i][p] = 0ULL;

    float4 a_s[4];
    float4 b_s;
#pragma unroll
    for (int t = 0; t < 4; t++) {
        float4 v = *(const float4*)(pA[t]);
        v.x *= iv[t]; v.y *= iv[t]; v.z *= iv[t]; v.w *= iv[t];
        *(float4*)(pA[t]) = v;          // write back normalized probs
        a_s[t] = v;
    }
    b_s = *(const float4*)(pB);

#define CTX_STORE(BUF) do {                                                \
    float* as = &As[BUF][0];                                               \
    _Pragma("unroll")                                                      \
    for (int t = 0; t < 4; t++) {                                          \
        as[(c4+0)*LDA + lrow + t*64] = a_s[t].x;                           \
        as[(c4+1)*LDA + lrow + t*64] = a_s[t].y;                           \
        as[(c4+2)*LDA + lrow + t*64] = a_s[t].z;                           \
        as[(c4+3)*LDA + lrow + t*64] = a_s[t].w;                           \
    }                                                                      \
    *(float4*)(&Bs[BUF][jr * LDB + dc]) = b_s;                             \
} while (0)

    CTX_STORE(0);
    __syncthreads();

    for (int it = 0; it < 128; it++) {
        const int buf = it & 1;
        if (it < 127) {
            const int k0 = (it + 1) * 16;
#pragma unroll
            for (int t = 0; t < 4; t++) {
                float4 v = *(const float4*)(pA[t] + k0);
                v.x *= iv[t]; v.y *= iv[t]; v.z *= iv[t]; v.w *= iv[t];
                *(float4*)(pA[t] + k0) = v;
                a_s[t] = v;
            }
            b_s = *(const float4*)(pB + (size_t)k0 * HD_);
        }
#pragma unroll
        for (int kk = 0; kk < 16; kk++) {
            const float* as = &As[buf][kk * LDA];
            const float* bs = &Bs[buf][kk * LDB];
            float4 a0 = *(const float4*)(as + ty * 8);
            float4 a1 = *(const float4*)(as + ty * 8 + 4);
            u64 ad[8];
            ad[0] = pk2(a0.x, a0.x); ad[1] = pk2(a0.y, a0.y);
            ad[2] = pk2(a0.z, a0.z); ad[3] = pk2(a0.w, a0.w);
            ad[4] = pk2(a1.x, a1.x); ad[5] = pk2(a1.y, a1.y);
            ad[6] = pk2(a1.z, a1.z); ad[7] = pk2(a1.w, a1.w);
            u64 b0 = *(const u64*)(bs + 0 * 16 + tx * 2);
            u64 b1 = *(const u64*)(bs + 1 * 16 + tx * 2);
            u64 b2 = *(const u64*)(bs + 2 * 16 + tx * 2);
            u64 b3 = *(const u64*)(bs + 3 * 16 + tx * 2);
#pragma unroll
            for (int i = 0; i < 8; i++) {
                fma2(acc[i][0], ad[i], b0);
                fma2(acc[i][1], ad[i], b1);
                fma2(acc[i][2], ad[i], b2);
                fma2(acc[i][3], ad[i], b3);
            }
        }
        if (it < 127) CTX_STORE(buf ^ 1);
        __syncthreads();
    }

    const int b = bh >> 4;
    const int h = bh & 15;
#pragma unroll
    for (int i = 0; i < 8; i++) {
        const int s = m0 + ty * 8 + i;
#pragma unroll
        for (int p = 0; p < 4; p++) {
            float2 v = up2(acc[i][p]);
            const int d = p * 16 + tx * 2;
            *(float2*)(g_ctx + ((size_t)(b * S_ + s)) * H_ + h * HD_ + d) = v;
        }
    }
#undef CTX_STORE
}

// ---------------------------------------------------------------------------
// Kernel 5: out[m,n] = sum_k ctx[m,k] Wo[n,k] + bo[n] + hidden[m,n]
// ---------------------------------------------------------------------------
__global__ void __launch_bounds__(256, 2) outproj_kernel(
    const float* __restrict__ W,
    const float* __restrict__ bias,
    const float* __restrict__ hid,
    float* __restrict__ out)
{
    constexpr int LDA = 132;
    __shared__ __align__(16) float As[2][16 * LDA];
    __shared__ __align__(16) float Bs[2][16 * LDA];

    const int tid = threadIdx.x;
    const int n0 = blockIdx.x * 128;
    const int m0 = blockIdx.y * 128;
    const int tx = tid & 15;
    const int ty = tid >> 4;
    const int lrow = tid >> 2;
    const int c4 = (tid & 3) * 4;

    const float* xA0 = g_ctx + (size_t)(m0 + lrow) * H_ + c4;
    const float* xA1 = xA0 + (size_t)64 * H_;
    const float* xB0 = W + (size_t)(n0 + lrow) * H_ + c4;
    const float* xB1 = xB0 + (size_t)64 * H_;

    u64 acc[8][4];
#pragma unroll
    for (int i = 0; i < 8; i++)
#pragma unroll
        for (int p = 0; p < 4; p++) acc[i][p] = 0ULL;

    float4 a0s = *(const float4*)(xA0);
    float4 a1s = *(const float4*)(xA1);
    float4 b0s = *(const float4*)(xB0);
    float4 b1s = *(const float4*)(xB1);

#define OP_STORE(BUF) do {                                                 \
    float* as = &As[BUF][0]; float* bs = &Bs[BUF][0];                      \
    as[(c4+0)*LDA + lrow]      = a0s.x; as[(c4+1)*LDA + lrow]      = a0s.y;\
    as[(c4+2)*LDA + lrow]      = a0s.z; as[(c4+3)*LDA + lrow]      = a0s.w;\
    as[(c4+0)*LDA + lrow + 64] = a1s.x; as[(c4+1)*LDA + lrow + 64] = a1s.y;\
    as[(c4+2)*LDA + lrow + 64] = a1s.z; as[(c4+3)*LDA + lrow + 64] = a1s.w;\
    bs[(c4+0)*LDA + lrow]      = b0s.x; bs[(c4+1)*LDA + lrow]      = b0s.y;\
    bs[(c4+2)*LDA + lrow]      = b0s.z; bs[(c4+3)*LDA + lrow]      = b0s.w;\
    bs[(c4+0)*LDA + lrow + 64] = b1s.x; bs[(c4+1)*LDA + lrow + 64] = b1s.y;\
    bs[(c4+2)*LDA + lrow + 64] = b1s.z; bs[(c4+3)*LDA + lrow + 64] = b1s.w;\
} while (0)

    OP_STORE(0);
    __syncthreads();

    for (int it = 0; it < 64; it++) {
        const int buf = it & 1;
        if (it < 63) {
            const int k0 = (it + 1) * 16;
            a0s = *(const float4*)(xA0 + k0);
            a1s = *(const float4*)(xA1 + k0);
            b0s = *(const float4*)(xB0 + k0);
            b1s = *(const float4*)(xB1 + k0);
        }
#pragma unroll
        for (int kk = 0; kk < 16; kk++) {
            const float* as = &As[buf][kk * LDA];
            const float* bs = &Bs[buf][kk * LDA];
            float4 a0 = *(const float4*)(as + ty * 8);
            float4 a1 = *(const float4*)(as + ty * 8 + 4);
            u64 ad[8];
            ad[0] = pk2(a0.x, a0.x); ad[1] = pk2(a0.y, a0.y);
            ad[2] = pk2(a0.z, a0.z); ad[3] = pk2(a0.w, a0.w);
            ad[4] = pk2(a1.x, a1.x); ad[5] = pk2(a1.y, a1.y);
            ad[6] = pk2(a1.z, a1.z); ad[7] = pk2(a1.w, a1.w);
            u64 b0 = *(const u64*)(bs + 0 * 32 + tx * 2);
            u64 b1 = *(const u64*)(bs + 1 * 32 + tx * 2);
            u64 b2 = *(const u64*)(bs + 2 * 32 + tx * 2);
            u64 b3 = *(const u64*)(bs + 3 * 32 + tx * 2);
#pragma unroll
            for (int i = 0; i < 8; i++) {
                fma2(acc[i][0], ad[i], b0);
                fma2(acc[i][1], ad[i], b1);
                fma2(acc[i][2], ad[i], b2);
                fma2(acc[i][3], ad[i], b3);
            }
        }
        if (it < 63) OP_STORE(buf ^ 1);
        __syncthreads();
    }

#pragma unroll
    for (int i = 0; i < 8; i++) {
        const int m = m0 + ty * 8 + i;
#pragma unroll
        for (int p = 0; p < 4; p++) {
            float2 v = up2(acc[i][p]);
            const int n = n0 + p * 32 + tx * 2;
            float2 bb = *(const float2*)(bias + n);
            float2 hh = *(const float2*)(hid + (size_t)m * H_ + n);
            v.x += bb.x + hh.x;
            v.y += bb.y + hh.y;
            *(float2*)(out + (size_t)m * H_ + n) = v;
        }
    }
#undef OP_STORE
}

// ---------------------------------------------------------------------------
extern "C" void kernel_launch(void* const* d_in, const int* in_sizes, int n_in,
                              void* d_out, int out_size)
{
    (void)in_sizes; (void)n_in;

    const float* hs = (const float*)d_in[0];
    const float* Wq = (const float*)d_in[1];
    const float* bq = (const float*)d_in[2];
    const float* Wk = (const float*)d_in[3];
    const float* bk = (const float*)d_in[4];
    const float* Wv = (const float*)d_in[5];
    const float* bv = (const float*)d_in[6];
    const float* Wo = (const float*)d_in[7];
    const float* bo = (const float*)d_in[8];
    float* out = (float*)d_out;

    float* probs;
    if ((long long)out_size >= OUT_ELEMS + PROBS_ELEMS) {
        probs = out + OUT_ELEMS;
    } else {
        void* p = nullptr;
        cudaGetSymbolAddress(&p, g_probs_fallback);
        probs = (float*)p;
    }

    proj_qkv_kernel<<<dim3(H_ / 128, M_ / 128, 3), 256>>>(hs, Wq, bq, Wk, bk, Wv, bv);
    scores_kernel<<<dim3(S_ / 128, S_ / 128, BH_), 256>>>(probs);
    rsum_kernel<<<(BH_ * S_) / 256, 256>>>();
    ctx_kernel<<<dim3(S_ / 256, BH_), 256>>>(probs);
    outproj_kernel<<<dim3(H_ / 128, M_ / 128), 256>>>(Wo, bo, hs, out);
}

// round 12
// speedup vs baseline: 1.4935x; 1.0008x over previous
#include <cuda_runtime.h>

// ---------------------------------------------------------------------------
// AttentionBlock (fp32 MHA): pproc(x,W,b) == x@W.T + b exactly in fwd pass.
// B=4, S=2048, H=1024, NH=16, HD=64. No scaling, no mask.
// Output buffer = [out (B,S,H)] ++ [probs (B,NH,S,S)], fp32.
//
// R9 version: double-buffered software-pipelined FFMA2 GEMMs (1 sync/iter,
// global prefetch overlapped with compute), softmax fused away:
//   scores writes exp(s-12) + deterministic partial row sums,
//   tiny kernel produces 1/rowsum,
//   ctx normalizes P at load time and writes normalized probs back in place.
// ---------------------------------------------------------------------------

namespace {
constexpr int B_  = 4;
constexpr int S_  = 2048;
constexpr int H_  = 1024;
constexpr int NH_ = 16;
constexpr int HD_ = 64;
constexpr int M_  = B_ * S_;          // 8192
constexpr int BH_ = B_ * NH_;         // 64
constexpr long long OUT_ELEMS   = (long long)M_ * H_;
constexpr long long PROBS_ELEMS = (long long)BH_ * S_ * S_;
}

// Scratch (device globals)
__device__ float g_q[M_ * H_];            // [BH][S][HD]
__device__ float g_k[M_ * H_];
__device__ float g_v[M_ * H_];
__device__ float g_ctx[M_ * H_];          // [B,S,H]
__device__ float g_psum[(long long)BH_ * S_ * 16];   // per-(row, n-tile) exp sums
__device__ float g_inv[BH_ * S_];         // 1 / row sum
__device__ float g_probs_fallback[268435456];

// ---------------- packed f32x2 FMA helpers --------------------------------
typedef unsigned long long u64;

__device__ __forceinline__ u64 pk2(float lo, float hi) {
    u64 r;
    asm("mov.b64 %0, {%1, %2};" : "=l"(r) : "f"(lo), "f"(hi));
    return r;
}
__device__ __forceinline__ void fma2(u64& d, u64 a, u64 b) {
    asm("fma.rn.f32x2 %0, %1, %2, %0;" : "+l"(d) : "l"(a), "l"(b));
}
__device__ __forceinline__ float2 up2(u64 v) {
    float2 r;
    asm("mov.b64 {%0, %1}, %2;" : "=f"(r.x), "=f"(r.y) : "l"(v));
    return r;
}

// ---------------------------------------------------------------------------
// Kernel 1: fused QKV projections (grid.z selects Q/K/V).
// C[m,n] = sum_k X[m,k] W[n,k] + bias[n], written as [BH][S][HD].
// 128x128 tile, BK=16, 256 threads, 8x8 per thread (cols n = p*32 + tx*2).
// ---------------------------------------------------------------------------
__global__ void __launch_bounds__(256, 2) proj_qkv_kernel(
    const float* __restrict__ X,
    const float* __restrict__ Wq, const float* __restrict__ Bq,
    const float* __restrict__ Wk, const float* __restrict__ Bk,
    const float* __restrict__ Wv, const float* __restrict__ Bv)
{
    const int sel = blockIdx.z;
    const float* W    = (sel == 0) ? Wq : (sel == 1) ? Wk : Wv;
    const float* bias = (sel == 0) ? Bq : (sel == 1) ? Bk : Bv;
    float* out        = (sel == 0) ? g_q : (sel == 1) ? g_k : g_v;

    constexpr int LDA = 132;
    __shared__ __align__(16) float As[2][16 * LDA];
    __shared__ __align__(16) float Bs[2][16 * LDA];

    const int tid = threadIdx.x;
    const int n0 = blockIdx.x * 128;
    const int m0 = blockIdx.y * 128;
    const int tx = tid & 15;
    const int ty = tid >> 4;
    const int lrow = tid >> 2;          // 0..63
    const int c4 = (tid & 3) * 4;

    const float* xA0 = X + (size_t)(m0 + lrow) * H_ + c4;
    const float* xA1 = xA0 + (size_t)64 * H_;
    const float* xB0 = W + (size_t)(n0 + lrow) * H_ + c4;
    const float* xB1 = xB0 + (size_t)64 * H_;

    u64 acc[8][4];
#pragma unroll
    for (int i = 0; i < 8; i++)
#pragma unroll
        for (int p = 0; p < 4; p++) acc[i][p] = 0ULL;

    float4 a0s = *(const float4*)(xA0);
    float4 a1s = *(const float4*)(xA1);
    float4 b0s = *(const float4*)(xB0);
    float4 b1s = *(const float4*)(xB1);

#define PROJ_STORE(BUF) do {                                               \
    float* as = &As[BUF][0]; float* bs = &Bs[BUF][0];                      \
    as[(c4+0)*LDA + lrow]      = a0s.x; as[(c4+1)*LDA + lrow]      = a0s.y;\
    as[(c4+2)*LDA + lrow]      = a0s.z; as[(c4+3)*LDA + lrow]      = a0s.w;\
    as[(c4+0)*LDA + lrow + 64] = a1s.x; as[(c4+1)*LDA + lrow + 64] = a1s.y;\
    as[(c4+2)*LDA + lrow + 64] = a1s.z; as[(c4+3)*LDA + lrow + 64] = a1s.w;\
    bs[(c4+0)*LDA + lrow]      = b0s.x; bs[(c4+1)*LDA + lrow]      = b0s.y;\
    bs[(c4+2)*LDA + lrow]      = b0s.z; bs[(c4+3)*LDA + lrow]      = b0s.w;\
    bs[(c4+0)*LDA + lrow + 64] = b1s.x; bs[(c4+1)*LDA + lrow + 64] = b1s.y;\
    bs[(c4+2)*LDA + lrow + 64] = b1s.z; bs[(c4+3)*LDA + lrow + 64] = b1s.w;\
} while (0)

    PROJ_STORE(0);
    __syncthreads();

    for (int it = 0; it < 64; it++) {
        const int buf = it & 1;
        if (it < 63) {
            const int k0 = (it + 1) * 16;
            a0s = *(const float4*)(xA0 + k0);
            a1s = *(const float4*)(xA1 + k0);
            b0s = *(const float4*)(xB0 + k0);
            b1s = *(const float4*)(xB1 + k0);
        }
#pragma unroll
        for (int kk = 0; kk < 16; kk++) {
            const float* as = &As[buf][kk * LDA];
            const float* bs = &Bs[buf][kk * LDA];
            float4 a0 = *(const float4*)(as + ty * 8);
            float4 a1 = *(const float4*)(as + ty * 8 + 4);
            u64 ad[8];
            ad[0] = pk2(a0.x, a0.x); ad[1] = pk2(a0.y, a0.y);
            ad[2] = pk2(a0.z, a0.z); ad[3] = pk2(a0.w, a0.w);
            ad[4] = pk2(a1.x, a1.x); ad[5] = pk2(a1.y, a1.y);
            ad[6] = pk2(a1.z, a1.z); ad[7] = pk2(a1.w, a1.w);
            u64 b0 = *(const u64*)(bs + 0 * 32 + tx * 2);
            u64 b1 = *(const u64*)(bs + 1 * 32 + tx * 2);
            u64 b2 = *(const u64*)(bs + 2 * 32 + tx * 2);
            u64 b3 = *(const u64*)(bs + 3 * 32 + tx * 2);
#pragma unroll
            for (int i = 0; i < 8; i++) {
                fma2(acc[i][0], ad[i], b0);
                fma2(acc[i][1], ad[i], b1);
                fma2(acc[i][2], ad[i], b2);
                fma2(acc[i][3], ad[i], b3);
            }
        }
        if (it < 63) PROJ_STORE(buf ^ 1);
        __syncthreads();
    }

#pragma unroll
    for (int i = 0; i < 8; i++) {
        const int m = m0 + ty * 8 + i;
        const int b = m >> 11;
        const int s = m & (S_ - 1);
#pragma unroll
        for (int p = 0; p < 4; p++) {
            float2 v = up2(acc[i][p]);
            const int n = n0 + p * 32 + tx * 2;
            float2 bb = *(const float2*)(bias + n);
            v.x += bb.x; v.y += bb.y;
            const int h = n >> 6, d = n & 63;
            *(float2*)(out + ((size_t)((b * NH_ + h) * S_ + s)) * HD_ + d) = v;
        }
    }
#undef PROJ_STORE
}

// ---------------------------------------------------------------------------
// Kernel 2: scores per (b,h): exp(Q K^T - 12) -> probs (unnormalized) plus
// deterministic per-(row, n-tile) partial sums.
// ---------------------------------------------------------------------------
__global__ void __launch_bounds__(256, 2) scores_kernel(float* __restrict__ probs)
{
    constexpr int LDA = 132;
    __shared__ __align__(16) float As[2][16 * LDA];
    __shared__ __align__(16) float Bs[2][16 * LDA];

    const int tid = threadIdx.x;
    const int n0 = blockIdx.x * 128;
    const int m0 = blockIdx.y * 128;
    const int bh = blockIdx.z;
    const float* Q = g_q + (size_t)bh * S_ * HD_;
    const float* K = g_k + (size_t)bh * S_ * HD_;

    const int tx = tid & 15;
    const int ty = tid >> 4;
    const int lrow = tid >> 2;
    const int c4 = (tid & 3) * 4;

    const float* xA0 = Q + (size_t)(m0 + lrow) * HD_ + c4;
    const float* xA1 = xA0 + (size_t)64 * HD_;
    const float* xB0 = K + (size_t)(n0 + lrow) * HD_ + c4;
    const float* xB1 = xB0 + (size_t)64 * HD_;

    u64 acc[8][4];
#pragma unroll
    for (int i = 0; i < 8; i++)
#pragma unroll
        for (int p = 0; p < 4; p++) acc[i][p] = 0ULL;

    float4 a0s = *(const float4*)(xA0);
    float4 a1s = *(const float4*)(xA1);
    float4 b0s = *(const float4*)(xB0);
    float4 b1s = *(const float4*)(xB1);

#define SC_STORE(BUF) do {                                                 \
    float* as = &As[BUF][0]; float* bs = &Bs[BUF][0];                      \
    as[(c4+0)*LDA + lrow]      = a0s.x; as[(c4+1)*LDA + lrow]      = a0s.y;\
    as[(c4+2)*LDA + lrow]      = a0s.z; as[(c4+3)*LDA + lrow]      = a0s.w;\
    as[(c4+0)*LDA + lrow + 64] = a1s.x; as[(c4+1)*LDA + lrow + 64] = a1s.y;\
    as[(c4+2)*LDA + lrow + 64] = a1s.z; as[(c4+3)*LDA + lrow + 64] = a1s.w;\
    bs[(c4+0)*LDA + lrow]      = b0s.x; bs[(c4+1)*LDA + lrow]      = b0s.y;\
    bs[(c4+2)*LDA + lrow]      = b0s.z; bs[(c4+3)*LDA + lrow]      = b0s.w;\
    bs[(c4+0)*LDA + lrow + 64] = b1s.x; bs[(c4+1)*LDA + lrow + 64] = b1s.y;\
    bs[(c4+2)*LDA + lrow + 64] = b1s.z; bs[(c4+3)*LDA + lrow + 64] = b1s.w;\
} while (0)

    SC_STORE(0);
    __syncthreads();

    for (int it = 0; it < 4; it++) {
        const int buf = it & 1;
        if (it < 3) {
            const int k0 = (it + 1) * 16;
            a0s = *(const float4*)(xA0 + k0);
            a1s = *(const float4*)(xA1 + k0);
            b0s = *(const float4*)(xB0 + k0);
            b1s = *(const float4*)(xB1 + k0);
        }
#pragma unroll
        for (int kk = 0; kk < 16; kk++) {
            const float* as = &As[buf][kk * LDA];
            const float* bs = &Bs[buf][kk * LDA];
            float4 a0 = *(const float4*)(as + ty * 8);
            float4 a1 = *(const float4*)(as + ty * 8 + 4);
            u64 ad[8];
            ad[0] = pk2(a0.x, a0.x); ad[1] = pk2(a0.y, a0.y);
            ad[2] = pk2(a0.z, a0.z); ad[3] = pk2(a0.w, a0.w);
            ad[4] = pk2(a1.x, a1.x); ad[5] = pk2(a1.y, a1.y);
            ad[6] = pk2(a1.z, a1.z); ad[7] = pk2(a1.w, a1.w);
            u64 b0 = *(const u64*)(bs + 0 * 32 + tx * 2);
            u64 b1 = *(const u64*)(bs + 1 * 32 + tx * 2);
            u64 b2 = *(const u64*)(bs + 2 * 32 + tx * 2);
            u64 b3 = *(const u64*)(bs + 3 * 32 + tx * 2);
#pragma unroll
            for (int i = 0; i < 8; i++) {
                fma2(acc[i][0], ad[i], b0);
                fma2(acc[i][1], ad[i], b1);
                fma2(acc[i][2], ad[i], b2);
                fma2(acc[i][3], ad[i], b3);
            }
        }
        if (it < 3) SC_STORE(buf ^ 1);
        __syncthreads();
    }

    // epilogue: exp(s - 12), store unnormalized, partial row sums
    float* P = probs + (size_t)bh * S_ * S_;
#pragma unroll
    for (int i = 0; i < 8; i++) {
        const int m = m0 + ty * 8 + i;
        float rs = 0.f;
#pragma unroll
        for (int p = 0; p < 4; p++) {
            float2 v = up2(acc[i][p]);
            v.x = __expf(v.x - 12.0f);
            v.y = __expf(v.y - 12.0f);
            rs += v.x + v.y;
            *(float2*)(P + (size_t)m * S_ + n0 + p * 32 + tx * 2) = v;
        }
        // reduce across the 16 tx lanes (xor offsets stay within 16-lane group)
#pragma unroll
        for (int o = 8; o; o >>= 1) rs += __shfl_xor_sync(0xffffffffu, rs, o);
        if (tx == 0)
            g_psum[((size_t)bh * S_ + m) * 16 + blockIdx.x] = rs;
    }
#undef SC_STORE
}

// ---------------------------------------------------------------------------
// Kernel 3: 1/rowsum (deterministic, 16 partials per row).
// ---------------------------------------------------------------------------
__global__ void __launch_bounds__(256) rsum_kernel()
{
    const int r = blockIdx.x * 256 + threadIdx.x;   // < 131072
    const float4* p = (const float4*)(g_psum + (size_t)r * 16);
    float4 a = p[0], b = p[1], c = p[2], d = p[3];
    float s = ((a.x + a.y) + (a.z + a.w)) + ((b.x + b.y) + (b.z + b.w))
            + ((c.x + c.y) + (c.z + c.w)) + ((d.x + d.y) + (d.z + d.w));
    g_inv[r] = 1.0f / s;
}

// ---------------------------------------------------------------------------
// Kernel 4: ctx = P_norm @ V per (b,h); P is normalized at load time and the
// normalized probs are written back in place. Tile 256x64, BK=16, 256 thr.
// ---------------------------------------------------------------------------
__global__ void __launch_bounds__(256, 2) ctx_kernel(float* __restrict__ probs)
{
    constexpr int LDA = 260;
    constexpr int LDB = 68;
    __shared__ __align__(16) float As[2][16 * LDA];
    __shared__ __align__(16) float Bs[2][16 * LDB];

    const int tid = threadIdx.x;
    const int tx = tid & 7;
    const int ty = tid >> 3;
    const int m0 = blockIdx.x * 256;
    const int bh = blockIdx.y;
    float* P = probs + (size_t)bh * S_ * S_;
    const float* V = g_v + (size_t)bh * S_ * HD_;

    const int lrow = tid >> 2;          // 0..63
    const int c4 = (tid & 3) * 4;

    float iv[4];
    float* pA[4];
#pragma unroll
    for (int t = 0; t < 4; t++) {
        const int r = m0 + lrow + t * 64;
        iv[t] = g_inv[bh * S_ + r];
        pA[t] = P + (size_t)r * S_ + c4;
    }
    const int jr = tid >> 4;
    const int dc = (tid & 15) * 4;
    const float* pB = V + (size_t)jr * HD_ + dc;

    u64 acc[8][4];
#pragma unroll
    for (int i = 0; i < 8; i++)
#pragma unroll
        for (int p = 0; p < 4; p++) acc[i][p] = 0ULL;

    float4 a_s[4];
    float4 b_s;
#pragma unroll
    for (int t = 0; t < 4; t++) {
        float4 v = *(const float4*)(pA[t]);
        v.x *= iv[t]; v.y *= iv[t]; v.z *= iv[t]; v.w *= iv[t];
        *(float4*)(pA[t]) = v;          // write back normalized probs
        a_s[t] = v;
    }
    b_s = *(const float4*)(pB);

#define CTX_STORE(BUF) do {                                                \
    float* as = &As[BUF][0];                                               \
    _Pragma("unroll")                                                      \
    for (int t = 0; t < 4; t++) {                                          \
        as[(c4+0)*LDA + lrow + t*64] = a_s[t].x;                           \
        as[(c4+1)*LDA + lrow + t*64] = a_s[t].y;                           \
        as[(c4+2)*LDA + lrow + t*64] = a_s[t].z;                           \
        as[(c4+3)*LDA + lrow + t*64] = a_s[t].w;                           \
    }                                                                      \
    *(float4*)(&Bs[BUF][jr * LDB + dc]) = b_s;                             \
} while (0)

    CTX_STORE(0);
    __syncthreads();

    for (int it = 0; it < 128; it++) {
        const int buf = it & 1;
        if (it < 127) {
            const int k0 = (it + 1) * 16;
#pragma unroll
            for (int t = 0; t < 4; t++) {
                float4 v = *(const float4*)(pA[t] + k0);
                v.x *= iv[t]; v.y *= iv[t]; v.z *= iv[t]; v.w *= iv[t];
                *(float4*)(pA[t] + k0) = v;
                a_s[t] = v;
            }
            b_s = *(const float4*)(pB + (size_t)k0 * HD_);
        }
#pragma unroll
        for (int kk = 0; kk < 16; kk++) {
            const float* as = &As[buf][kk * LDA];
            const float* bs = &Bs[buf][kk * LDB];
            float4 a0 = *(const float4*)(as + ty * 8);
            float4 a1 = *(const float4*)(as + ty * 8 + 4);
            u64 ad[8];
            ad[0] = pk2(a0.x, a0.x); ad[1] = pk2(a0.y, a0.y);
            ad[2] = pk2(a0.z, a0.z); ad[3] = pk2(a0.w, a0.w);
            ad[4] = pk2(a1.x, a1.x); ad[5] = pk2(a1.y, a1.y);
            ad[6] = pk2(a1.z, a1.z); ad[7] = pk2(a1.w, a1.w);
            u64 b0 = *(const u64*)(bs + 0 * 16 + tx * 2);
            u64 b1 = *(const u64*)(bs + 1 * 16 + tx * 2);
            u64 b2 = *(const u64*)(bs + 2 * 16 + tx * 2);
            u64 b3 = *(const u64*)(bs + 3 * 16 + tx * 2);
#pragma unroll
            for (int i = 0; i < 8; i++) {
                fma2(acc[i][0], ad[i], b0);
                fma2(acc[i][1], ad[i], b1);
                fma2(acc[i][2], ad[i], b2);
                fma2(acc[i][3], ad[i], b3);
            }
        }
        if (it < 127) CTX_STORE(buf ^ 1);
        __syncthreads();
    }

    const int b = bh >> 4;
    const int h = bh & 15;
#pragma unroll
    for (int i = 0; i < 8; i++) {
        const int s = m0 + ty * 8 + i;
#pragma unroll
        for (int p = 0; p < 4; p++) {
            float2 v = up2(acc[i][p]);
            const int d = p * 16 + tx * 2;
            *(float2*)(g_ctx + ((size_t)(b * S_ + s)) * H_ + h * HD_ + d) = v;
        }
    }
#undef CTX_STORE
}

// ---------------------------------------------------------------------------
// Kernel 5: out[m,n] = sum_k ctx[m,k] Wo[n,k] + bo[n] + hidden[m,n]
// ---------------------------------------------------------------------------
__global__ void __launch_bounds__(256, 2) outproj_kernel(
    const float* __restrict__ W,
    const float* __restrict__ bias,
    const float* __restrict__ hid,
    float* __restrict__ out)
{
    constexpr int LDA = 132;
    __shared__ __align__(16) float As[2][16 * LDA];
    __shared__ __align__(16) float Bs[2][16 * LDA];

    const int tid = threadIdx.x;
    const int n0 = blockIdx.x * 128;
    const int m0 = blockIdx.y * 128;
    const int tx = tid & 15;
    const int ty = tid >> 4;
    const int lrow = tid >> 2;
    const int c4 = (tid & 3) * 4;

    const float* xA0 = g_ctx + (size_t)(m0 + lrow) * H_ + c4;
    const float* xA1 = xA0 + (size_t)64 * H_;
    const float* xB0 = W + (size_t)(n0 + lrow) * H_ + c4;
    const float* xB1 = xB0 + (size_t)64 * H_;

    u64 acc[8][4];
#pragma unroll
    for (int i = 0; i < 8; i++)
#pragma unroll
        for (int p = 0; p < 4; p++) acc[i][p] = 0ULL;

    float4 a0s = *(const float4*)(xA0);
    float4 a1s = *(const float4*)(xA1);
    float4 b0s = *(const float4*)(xB0);
    float4 b1s = *(const float4*)(xB1);

#define OP_STORE(BUF) do {                                                 \
    float* as = &As[BUF][0]; float* bs = &Bs[BUF][0];                      \
    as[(c4+0)*LDA + lrow]      = a0s.x; as[(c4+1)*LDA + lrow]      = a0s.y;\
    as[(c4+2)*LDA + lrow]      = a0s.z; as[(c4+3)*LDA + lrow]      = a0s.w;\
    as[(c4+0)*LDA + lrow + 64] = a1s.x; as[(c4+1)*LDA + lrow + 64] = a1s.y;\
    as[(c4+2)*LDA + lrow + 64] = a1s.z; as[(c4+3)*LDA + lrow + 64] = a1s.w;\
    bs[(c4+0)*LDA + lrow]      = b0s.x; bs[(c4+1)*LDA + lrow]      = b0s.y;\
    bs[(c4+2)*LDA + lrow]      = b0s.z; bs[(c4+3)*LDA + lrow]      = b0s.w;\
    bs[(c4+0)*LDA + lrow + 64] = b1s.x; bs[(c4+1)*LDA + lrow + 64] = b1s.y;\
    bs[(c4+2)*LDA + lrow + 64] = b1s.z; bs[(c4+3)*LDA + lrow + 64] = b1s.w;\
} while (0)

    OP_STORE(0);
    __syncthreads();

    for (int it = 0; it < 64; it++) {
        const int buf = it & 1;
        if (it < 63) {
            const int k0 = (it + 1) * 16;
            a0s = *(const float4*)(xA0 + k0);
            a1s = *(const float4*)(xA1 + k0);
            b0s = *(const float4*)(xB0 + k0);
            b1s = *(const float4*)(xB1 + k0);
        }
#pragma unroll
        for (int kk = 0; kk < 16; kk++) {
            const float* as = &As[buf][kk * LDA];
            const float* bs = &Bs[buf][kk * LDA];
            float4 a0 = *(const float4*)(as + ty * 8);
            float4 a1 = *(const float4*)(as + ty * 8 + 4);
            u64 ad[8];
            ad[0] = pk2(a0.x, a0.x); ad[1] = pk2(a0.y, a0.y);
            ad[2] = pk2(a0.z, a0.z); ad[3] = pk2(a0.w, a0.w);
            ad[4] = pk2(a1.x, a1.x); ad[5] = pk2(a1.y, a1.y);
            ad[6] = pk2(a1.z, a1.z); ad[7] = pk2(a1.w, a1.w);
            u64 b0 = *(const u64*)(bs + 0 * 32 + tx * 2);
            u64 b1 = *(const u64*)(bs + 1 * 32 + tx * 2);
            u64 b2 = *(const u64*)(bs + 2 * 32 + tx * 2);
            u64 b3 = *(const u64*)(bs + 3 * 32 + tx * 2);
#pragma unroll
            for (int i = 0; i < 8; i++) {
                fma2(acc[i][0], ad[i], b0);
                fma2(acc[i][1], ad[i], b1);
                fma2(acc[i][2], ad[i], b2);
                fma2(acc[i][3], ad[i], b3);
            }
        }
        if (it < 63) OP_STORE(buf ^ 1);
        __syncthreads();
    }

#pragma unroll
    for (int i = 0; i < 8; i++) {
        const int m = m0 + ty * 8 + i;
#pragma unroll
        for (int p = 0; p < 4; p++) {
            float2 v = up2(acc[i][p]);
            const int n = n0 + p * 32 + tx * 2;
            float2 bb = *(const float2*)(bias + n);
            float2 hh = *(const float2*)(hid + (size_t)m * H_ + n);
            v.x += bb.x + hh.x;
            v.y += bb.y + hh.y;
            *(float2*)(out + (size_t)m * H_ + n) = v;
        }
    }
#undef OP_STORE
}

// ---------------------------------------------------------------------------
extern "C" void kernel_launch(void* const* d_in, const int* in_sizes, int n_in,
                              void* d_out, int out_size)
{
    (void)in_sizes; (void)n_in;

    const float* hs = (const float*)d_in[0];
    const float* Wq = (const float*)d_in[1];
    const float* bq = (const float*)d_in[2];
    const float* Wk = (const float*)d_in[3];
    const float* bk = (const float*)d_in[4];
    const float* Wv = (const float*)d_in[5];
    const float* bv = (const float*)d_in[6];
    const float* Wo = (const float*)d_in[7];
    const float* bo = (const float*)d_in[8];
    float* out = (float*)d_out;

    float* probs;
    if ((long long)out_size >= OUT_ELEMS + PROBS_ELEMS) {
        probs = out + OUT_ELEMS;
    } else {
        void* p = nullptr;
        cudaGetSymbolAddress(&p, g_probs_fallback);
        probs = (float*)p;
    }

    proj_qkv_kernel<<<dim3(H_ / 128, M_ / 128, 3), 256>>>(hs, Wq, bq, Wk, bk, Wv, bv);
    scores_kernel<<<dim3(S_ / 128, S_ / 128, BH_), 256>>>(probs);
    rsum_kernel<<<(BH_ * S_) / 256, 256>>>();
    ctx_kernel<<<dim3(S_ / 256, BH_), 256>>>(probs);
    outproj_kernel<<<dim3(H_ / 128, M_ / 128), 256>>>(Wo, bo, hs, out);
}